// round 4
// baseline (speedup 1.0000x reference)
#include <cuda_runtime.h>
#include <cuda_bf16.h>
#include <math.h>
#include <stdint.h>

#define BB      4
#define SS      2048
#define DMODEL  1024
#define NH      16
#define HDIM    64
#define MR      (BB*SS)

// ---------------------------------------------------------------------------
// Scratch
// ---------------------------------------------------------------------------
__device__ float g_Qp[MR*DMODEL];
__device__ float g_Kp[MR*DMODEL];
__device__ float g_Vp[MR*DMODEL];
__device__ float g_Ao[MR*DMODEL];
__device__ float g_cm[BB*NH*SS];
__device__ float g_cr[BB*NH*SS];

// ---------------------------------------------------------------------------
// bf16 split helpers: x = hi + lo with ~16-bit effective mantissa
// ---------------------------------------------------------------------------
__device__ __forceinline__ void split2(float x, float y, uint32_t& hi, uint32_t& lo){
    __nv_bfloat16 hx = __float2bfloat16(x);
    __nv_bfloat16 hy = __float2bfloat16(y);
    float rx = x - __bfloat162float(hx);
    float ry = y - __bfloat162float(hy);
    __nv_bfloat162 h2 = __halves2bfloat162(hx, hy);
    __nv_bfloat162 l2 = __halves2bfloat162(__float2bfloat16(rx), __float2bfloat16(ry));
    hi = *reinterpret_cast<uint32_t*>(&h2);
    lo = *reinterpret_cast<uint32_t*>(&l2);
}

// mma.m16n8k16 bf16: D += A*B (fp32 accum)
__device__ __forceinline__ void mma16(float* d,
    uint32_t a0, uint32_t a1, uint32_t a2, uint32_t a3,
    uint32_t b0, uint32_t b1)
{
    asm volatile(
        "mma.sync.aligned.m16n8k16.row.col.f32.bf16.bf16.f32 "
        "{%0,%1,%2,%3}, {%4,%5,%6,%7}, {%8,%9}, {%0,%1,%2,%3};\n"
        : "+f"(d[0]), "+f"(d[1]), "+f"(d[2]), "+f"(d[3])
        : "r"(a0), "r"(a1), "r"(a2), "r"(a3), "r"(b0), "r"(b1));
}

// ---------------------------------------------------------------------------
// Kernel 1: C = A[M,K] @ W[K,N] + bias, 3-pass split-bf16.
// Block 128x128, BK=16, 256 thr = 8 warps (2x4), warp tile 64x32.
// Fragment-permuted smem (u32 = bf16 pair along k).
// A-perm off: ((mt*NKC+kc)*32 + (m&7)*4 + ((k&7)>>1))*4 + ((k>>3)&1)*2 + ((m>>3)&1)
// B-perm off: ((nt*NKC+kc)*32 + (n&7)*4 + ((k&7)>>1))*2 + ((k>>3)&1)
// ---------------------------------------------------------------------------
__global__ __launch_bounds__(256) void proj_bf(
    const float* __restrict__ A, const float* __restrict__ W,
    const float* __restrict__ bias, float* __restrict__ C,
    int M, int N, int K)
{
    __shared__ uint32_t AhU[1024], AlU[1024], BhU[1024], BlU[1024];
    const int tid = threadIdx.x, lane = tid & 31, w = tid >> 5;
    const int wy = w >> 2, wx = w & 3;
    const int brow = blockIdx.y << 7, bcol = blockIdx.x << 7;

    float acc[4][4][4];
#pragma unroll
    for (int mt = 0; mt < 4; mt++)
#pragma unroll
        for (int nt = 0; nt < 4; nt++)
#pragma unroll
            for (int j = 0; j < 4; j++) acc[mt][nt][j] = 0.f;

    const int am = tid >> 2, ak = (tid & 3) << 2;
    const float* ApA = A + (size_t)(brow + am) * K + ak;
    const float* ApB = ApA + (size_t)64 * K;
    const int wk = (tid >> 5) << 1, wn = (tid & 31) << 2;
    const float* Wp = W + (size_t)wk * N + bcol + wn;

    float4 avA = *(const float4*)ApA;
    float4 avB = *(const float4*)ApB;
    float4 wv0 = *(const float4*)Wp;
    float4 wv1 = *(const float4*)(Wp + N);

    // staging offsets (k-invariant parts)
    const int aoff = ((am >> 4) * 32 + ((am & 7) << 2) + ((ak & 7) >> 1)) * 4
                     + (((ak >> 3) & 1) << 1) + ((am >> 3) & 1);

    for (int k0 = 0; k0 < K; k0 += 16) {
        {
            uint32_t h, l;
            split2(avA.x, avA.y, h, l); AhU[aoff]       = h; AlU[aoff]       = l;
            split2(avA.z, avA.w, h, l); AhU[aoff+4]     = h; AlU[aoff+4]     = l;
            split2(avB.x, avB.y, h, l); AhU[aoff+512]   = h; AlU[aoff+512]   = l;
            split2(avB.z, avB.w, h, l); AhU[aoff+516]   = h; AlU[aoff+516]   = l;
            float w0a[4] = {wv0.x, wv0.y, wv0.z, wv0.w};
            float w1a[4] = {wv1.x, wv1.y, wv1.z, wv1.w};
#pragma unroll
            for (int j = 0; j < 4; j++) {
                int nn = wn + j;
                int offb = ((nn >> 3) * 32 + ((nn & 7) << 2) + ((wk & 7) >> 1)) * 2
                           + ((wk >> 3) & 1);
                split2(w0a[j], w1a[j], h, l); BhU[offb] = h; BlU[offb] = l;
            }
        }
        __syncthreads();
        if (k0 + 16 < K) {
            avA = *(const float4*)(ApA + k0 + 16);
            avB = *(const float4*)(ApB + k0 + 16);
            wv0 = *(const float4*)(Wp + (size_t)(k0 + 16) * N);
            wv1 = *(const float4*)(Wp + (size_t)(k0 + 17) * N);
        }
        uint4 ah[4], al[4]; uint2 bh[4], bl[4];
#pragma unroll
        for (int mt = 0; mt < 4; mt++) {
            int o = ((wy*4 + mt)*32 + lane)*4;
            ah[mt] = *(const uint4*)&AhU[o];
            al[mt] = *(const uint4*)&AlU[o];
        }
#pragma unroll
        for (int nt = 0; nt < 4; nt++) {
            int o = ((wx*4 + nt)*32 + lane)*2;
            bh[nt] = *(const uint2*)&BhU[o];
            bl[nt] = *(const uint2*)&BlU[o];
        }
#pragma unroll
        for (int mt = 0; mt < 4; mt++)
#pragma unroll
            for (int nt = 0; nt < 4; nt++) {
                mma16(acc[mt][nt], ah[mt].x, ah[mt].y, ah[mt].z, ah[mt].w, bh[nt].x, bh[nt].y);
                mma16(acc[mt][nt], al[mt].x, al[mt].y, al[mt].z, al[mt].w, bh[nt].x, bh[nt].y);
                mma16(acc[mt][nt], ah[mt].x, ah[mt].y, ah[mt].z, ah[mt].w, bl[nt].x, bl[nt].y);
            }
        __syncthreads();
    }

#pragma unroll
    for (int mt = 0; mt < 4; mt++)
#pragma unroll
        for (int nt = 0; nt < 4; nt++) {
            int row = brow + wy*64 + mt*16 + (lane >> 2);
            int col = bcol + wx*32 + nt*8 + ((lane & 3) << 1);
            float b0 = bias[col], b1 = bias[col+1];
            *(float2*)(C + (size_t)row*N + col) =
                make_float2(acc[mt][nt][0]+b0, acc[mt][nt][1]+b1);
            *(float2*)(C + (size_t)(row+8)*N + col) =
                make_float2(acc[mt][nt][2]+b0, acc[mt][nt][3]+b1);
        }
}

// ---------------------------------------------------------------------------
// Kernel 2: column softmax stats (max over q, sumexp over q) per key column.
// grid (BH=64, 16 key-tiles of 128); block 256 = 8 warps; warp owns 16 keys.
// K fragments resident in regs; Q tiles streamed through perm smem.
// ---------------------------------------------------------------------------
__global__ __launch_bounds__(256) void colstats_bf(
    const float* __restrict__ Qp, const float* __restrict__ Kp,
    float* __restrict__ cm, float* __restrict__ cr)
{
    __shared__ uint32_t SH[4096], SL[4096];
    const int tid = threadIdx.x, lane = tid & 31, w = tid >> 5;
    const int bh = blockIdx.x, kt0 = blockIdx.y << 7;
    const int b = bh >> 4, h = bh & 15;
    const size_t base = (size_t)b * SS * DMODEL + (size_t)h * HDIM;

    // stage K tile [128key x 64d] -> B-perm (NKC=4)
#pragma unroll
    for (int it = 0; it < 8; it++) {
        int u = it*256 + tid;
        int key = u >> 4, d = (u & 15) << 2;
        float4 v = *(const float4*)(Kp + base + (size_t)(kt0+key)*DMODEL + d);
        int off = (((key>>3)*4 + (d>>4))*32 + ((key&7)<<2) + ((d&7)>>1))*2 + ((d>>3)&1);
        uint32_t hh, ll;
        split2(v.x, v.y, hh, ll); SH[off]   = hh; SL[off]   = ll;
        split2(v.z, v.w, hh, ll); SH[off+2] = hh; SL[off+2] = ll;
    }
    __syncthreads();
    uint2 kbh[2][4], kbl[2][4];
#pragma unroll
    for (int nt2 = 0; nt2 < 2; nt2++)
#pragma unroll
        for (int kc = 0; kc < 4; kc++) {
            int o = (((w*2 + nt2)*4 + kc)*32 + lane)*2;
            kbh[nt2][kc] = *(const uint2*)&SH[o];
            kbl[nt2][kc] = *(const uint2*)&SL[o];
        }
    __syncthreads();   // done reading K; smem reused for Q

    float mst[4] = {-1e30f, -1e30f, -1e30f, -1e30f};
    float zst[4] = {0.f, 0.f, 0.f, 0.f};

    for (int qt = 0; qt < 16; qt++) {
        // stage Q tile [128q x 64d] -> A-perm (NKC=4)
#pragma unroll
        for (int it = 0; it < 8; it++) {
            int u = it*256 + tid;
            int q = u >> 4, d = (u & 15) << 2;
            float4 v = *(const float4*)(Qp + base + (size_t)(qt*128 + q)*DMODEL + d);
            int off = (((q>>4)*4 + (d>>4))*32 + ((q&7)<<2) + ((d&7)>>1))*4
                      + (((d>>3)&1)<<1) + ((q>>3)&1);
            uint32_t hh, ll;
            split2(v.x, v.y, hh, ll); SH[off]   = hh; SL[off]   = ll;
            split2(v.z, v.w, hh, ll); SH[off+4] = hh; SL[off+4] = ll;
        }
        __syncthreads();

        float acc[8][2][4];
#pragma unroll
        for (int mt = 0; mt < 8; mt++)
#pragma unroll
            for (int nt2 = 0; nt2 < 2; nt2++)
#pragma unroll
                for (int j = 0; j < 4; j++) acc[mt][nt2][j] = 0.f;

#pragma unroll
        for (int mt = 0; mt < 8; mt++)
#pragma unroll
            for (int kc = 0; kc < 4; kc++) {
                int o = ((mt*4 + kc)*32 + lane)*4;
                uint4 qh = *(const uint4*)&SH[o];
                uint4 ql = *(const uint4*)&SL[o];
#pragma unroll
                for (int nt2 = 0; nt2 < 2; nt2++) {
                    mma16(acc[mt][nt2], qh.x,qh.y,qh.z,qh.w, kbh[nt2][kc].x, kbh[nt2][kc].y);
                    mma16(acc[mt][nt2], ql.x,ql.y,ql.z,ql.w, kbh[nt2][kc].x, kbh[nt2][kc].y);
                    mma16(acc[mt][nt2], qh.x,qh.y,qh.z,qh.w, kbl[nt2][kc].x, kbl[nt2][kc].y);
                }
            }

        // online column stats; thread cols = 2*(lane&3)+{0,1}; reduce over g
#pragma unroll
        for (int nt2 = 0; nt2 < 2; nt2++)
#pragma unroll
            for (int hh = 0; hh < 2; hh++) {
                int si = nt2*2 + hh;
                float tmax = -1e30f;
#pragma unroll
                for (int mt = 0; mt < 8; mt++)
                    tmax = fmaxf(tmax, fmaxf(acc[mt][nt2][hh], acc[mt][nt2][hh+2]));
                tmax = fmaxf(tmax, __shfl_xor_sync(0xffffffffu, tmax, 4));
                tmax = fmaxf(tmax, __shfl_xor_sync(0xffffffffu, tmax, 8));
                tmax = fmaxf(tmax, __shfl_xor_sync(0xffffffffu, tmax, 16));
                float mn = fmaxf(mst[si], tmax);
                float ts = 0.f;
#pragma unroll
                for (int mt = 0; mt < 8; mt++)
                    ts += __expf(acc[mt][nt2][hh] - mn) + __expf(acc[mt][nt2][hh+2] - mn);
                ts += __shfl_xor_sync(0xffffffffu, ts, 4);
                ts += __shfl_xor_sync(0xffffffffu, ts, 8);
                ts += __shfl_xor_sync(0xffffffffu, ts, 16);
                zst[si] = zst[si] * __expf(mst[si] - mn) + ts;
                mst[si] = mn;
            }
        __syncthreads();   // before next Q staging overwrites SH/SL
    }

    if (lane < 4) {
#pragma unroll
        for (int nt2 = 0; nt2 < 2; nt2++)
#pragma unroll
            for (int hh = 0; hh < 2; hh++) {
                int col = kt0 + w*16 + nt2*8 + lane*2 + hh;
                cm[(size_t)bh*SS + col] = mst[nt2*2 + hh];
                cr[(size_t)bh*SS + col] = 1.0f / (8.0f * zst[nt2*2 + hh]);
            }
    }
}

// ---------------------------------------------------------------------------
// Kernel 3: fused score recompute + exp-scale + E@V. E stays in registers
// (C-frag lane map == A-frag lane map). k-tile 64. 2 syncs/iter.
// grid (BH=64, 16 q-tiles); block 256 = 8 warps; warp owns 16 q rows.
// ---------------------------------------------------------------------------
#define ATT_U32   (16384 + 128)
#define ATT_BYTES (ATT_U32*4)

__global__ __launch_bounds__(256) void attn_bf(
    const float* __restrict__ Qp, const float* __restrict__ Kp,
    const float* __restrict__ Vp, const float* __restrict__ cm,
    const float* __restrict__ cr, float* __restrict__ Ao)
{
    extern __shared__ uint32_t su[];
    uint32_t* QhU = su;               // 4096
    uint32_t* QlU = su + 4096;        // 4096
    uint32_t* KhU = su + 8192;        // 2048
    uint32_t* KlU = su + 10240;       // 2048
    uint32_t* VhU = su + 12288;       // 2048
    uint32_t* VlU = su + 14336;       // 2048
    float*    mS  = (float*)(su + 16384);   // 64
    float*    rS  = (float*)(su + 16448);   // 64

    const int tid = threadIdx.x, lane = tid & 31, w = tid >> 5;
    const int g = lane >> 2, t = lane & 3;
    const int bh = blockIdx.x, qt0 = blockIdx.y << 7;
    const int b = bh >> 4, h = bh & 15;
    const size_t base = (size_t)b * SS * DMODEL + (size_t)h * HDIM;

    // stage Q tile [128q x 64d] -> A-perm (resident)
#pragma unroll
    for (int it = 0; it < 8; it++) {
        int u = it*256 + tid;
        int q = u >> 4, d = (u & 15) << 2;
        float4 v = *(const float4*)(Qp + base + (size_t)(qt0 + q)*DMODEL + d);
        int off = (((q>>4)*4 + (d>>4))*32 + ((q&7)<<2) + ((d&7)>>1))*4
                  + (((d>>3)&1)<<1) + ((q>>3)&1);
        uint32_t hh, ll;
        split2(v.x, v.y, hh, ll); QhU[off]   = hh; QlU[off]   = ll;
        split2(v.z, v.w, hh, ll); QhU[off+4] = hh; QlU[off+4] = ll;
    }

    float accO[8][4];
#pragma unroll
    for (int nt = 0; nt < 8; nt++)
#pragma unroll
        for (int j = 0; j < 4; j++) accO[nt][j] = 0.f;

    for (int kt = 0; kt < 32; kt++) {
        const int k0 = kt << 6;
        __syncthreads();   // prev iter's mma reads done (iter0: Q staging done)

        // stage K [64key x 64d] -> B-perm (k-dim = d)
#pragma unroll
        for (int it = 0; it < 4; it++) {
            int u = it*256 + tid;
            int key = u >> 4, d = (u & 15) << 2;
            float4 kv = *(const float4*)(Kp + base + (size_t)(k0 + key)*DMODEL + d);
            int off = (((key>>3)*4 + (d>>4))*32 + ((key&7)<<2) + ((d&7)>>1))*2 + ((d>>3)&1);
            uint32_t hh, ll;
            split2(kv.x, kv.y, hh, ll); KhU[off]   = hh; KlU[off]   = ll;
            split2(kv.z, kv.w, hh, ll); KhU[off+2] = hh; KlU[off+2] = ll;
        }
        // stage V [64key x 64d] -> B-perm (k-dim = key, n-dim = d)
#pragma unroll
        for (int it = 0; it < 2; it++) {
            int u = it*256 + tid;
            int key = (u >> 4) << 1, d = (u & 15) << 2;
            float4 v0 = *(const float4*)(Vp + base + (size_t)(k0 + key)*DMODEL + d);
            float4 v1 = *(const float4*)(Vp + base + (size_t)(k0 + key + 1)*DMODEL + d);
            float a0[4] = {v0.x, v0.y, v0.z, v0.w};
            float a1[4] = {v1.x, v1.y, v1.z, v1.w};
#pragma unroll
            for (int j = 0; j < 4; j++) {
                int dd = d + j;
                int off = (((dd>>3)*4 + (key>>4))*32 + ((dd&7)<<2) + ((key&7)>>1))*2
                          + ((key>>3)&1);
                uint32_t hh, ll;
                split2(a0[j], a1[j], hh, ll); VhU[off] = hh; VlU[off] = ll;
            }
        }
        if (tid < 64) {
            mS[tid] = cm[(size_t)bh*SS + k0 + tid];
            rS[tid] = cr[(size_t)bh*SS + k0 + tid];
        }
        __syncthreads();

        // S = Q K^T for warp's 16 q rows x 64 keys
        float accs[8][4];
#pragma unroll
        for (int nt = 0; nt < 8; nt++)
#pragma unroll
            for (int j = 0; j < 4; j++) accs[nt][j] = 0.f;

#pragma unroll
        for (int kc = 0; kc < 4; kc++) {
            int oq = ((w*4 + kc)*32 + lane)*4;
            uint4 qh = *(const uint4*)&QhU[oq];
            uint4 ql = *(const uint4*)&QlU[oq];
#pragma unroll
            for (int nt = 0; nt < 8; nt++) {
                int ob = ((nt*4 + kc)*32 + lane)*2;
                uint2 kb = *(const uint2*)&KhU[ob];
                uint2 kl = *(const uint2*)&KlU[ob];
                mma16(accs[nt], qh.x,qh.y,qh.z,qh.w, kb.x, kb.y);
                mma16(accs[nt], ql.x,ql.y,ql.z,ql.w, kb.x, kb.y);
                mma16(accs[nt], qh.x,qh.y,qh.z,qh.w, kl.x, kl.y);
            }
        }

        // E = exp(s - m[k]) * r[k]; pure in-register repack C-frag -> A-frag
        uint32_t EH[4][4], EL[4][4];
#pragma unroll
        for (int nt = 0; nt < 8; nt++) {
            int kcp = nt >> 1, rb = (nt & 1) << 1;
            int c0 = nt*8 + t*2, c1 = c0 + 1;
            float m0 = mS[c0], m1 = mS[c1], r0 = rS[c0], r1 = rS[c1];
            float e00 = __expf(accs[nt][0] - m0) * r0;
            float e01 = __expf(accs[nt][1] - m1) * r1;
            float e10 = __expf(accs[nt][2] - m0) * r0;
            float e11 = __expf(accs[nt][3] - m1) * r1;
            uint32_t hh, ll;
            split2(e00, e01, hh, ll); EH[kcp][rb]   = hh; EL[kcp][rb]   = ll;
            split2(e10, e11, hh, ll); EH[kcp][rb+1] = hh; EL[kcp][rb+1] = ll;
        }

        // O += E @ V
#pragma unroll
        for (int kc = 0; kc < 4; kc++) {
#pragma unroll
            for (int nt = 0; nt < 8; nt++) {
                int ob = ((nt*4 + kc)*32 + lane)*2;
                uint2 vh = *(const uint2*)&VhU[ob];
                uint2 vl = *(const uint2*)&VlU[ob];
                mma16(accO[nt], EH[kc][0], EH[kc][1], EH[kc][2], EH[kc][3], vh.x, vh.y);
                mma16(accO[nt], EL[kc][0], EL[kc][1], EL[kc][2], EL[kc][3], vh.x, vh.y);
                mma16(accO[nt], EH[kc][0], EH[kc][1], EH[kc][2], EH[kc][3], vl.x, vl.y);
            }
        }
    }

    // write O tile, merged-head layout [b, q, h*64+d]
    const int row = qt0 + w*16 + g;
#pragma unroll
    for (int nt = 0; nt < 8; nt++) {
        int col = nt*8 + t*2;
        *(float2*)(Ao + base + (size_t)row*DMODEL + col) =
            make_float2(accO[nt][0], accO[nt][1]);
        *(float2*)(Ao + base + (size_t)(row+8)*DMODEL + col) =
            make_float2(accO[nt][2], accO[nt][3]);
    }
}

// ---------------------------------------------------------------------------
// Launch
// ---------------------------------------------------------------------------
extern "C" void kernel_launch(void* const* d_in, const int* in_sizes, int n_in,
                              void* d_out, int out_size)
{
    const float* qin = (const float*)d_in[0];
    const float* kin = (const float*)d_in[1];
    const float* vin = (const float*)d_in[2];
    const float* Wq  = (const float*)d_in[3];
    const float* bq  = (const float*)d_in[4];
    const float* Wk  = (const float*)d_in[5];
    const float* bk  = (const float*)d_in[6];
    const float* Wv  = (const float*)d_in[7];
    const float* bv  = (const float*)d_in[8];
    const float* Wo  = (const float*)d_in[9];
    const float* bo  = (const float*)d_in[10];

    float *Qp, *Kp, *Vp, *Ao, *cm, *cr;
    cudaGetSymbolAddress((void**)&Qp, g_Qp);
    cudaGetSymbolAddress((void**)&Kp, g_Kp);
    cudaGetSymbolAddress((void**)&Vp, g_Vp);
    cudaGetSymbolAddress((void**)&Ao, g_Ao);
    cudaGetSymbolAddress((void**)&cm, g_cm);
    cudaGetSymbolAddress((void**)&cr, g_cr);

    cudaFuncSetAttribute(attn_bf, cudaFuncAttributeMaxDynamicSharedMemorySize,
                         ATT_BYTES);

    dim3 gGemm(DMODEL/128, MR/128);   // (8, 64)

    proj_bf<<<gGemm, 256>>>(qin, Wq, bq, Qp, MR, DMODEL, DMODEL);
    proj_bf<<<gGemm, 256>>>(kin, Wk, bk, Kp, MR, DMODEL, DMODEL);
    proj_bf<<<gGemm, 256>>>(vin, Wv, bv, Vp, MR, DMODEL, DMODEL);

    colstats_bf<<<dim3(BB*NH, SS/128), 256>>>(Qp, Kp, cm, cr);

    attn_bf<<<dim3(BB*NH, SS/128), 256, ATT_BYTES>>>(Qp, Kp, Vp, cm, cr, Ao);

    proj_bf<<<gGemm, 256>>>(Ao, Wo, bo, (float*)d_out, MR, DMODEL, DMODEL);
}

// round 6
// speedup vs baseline: 1.6224x; 1.6224x over previous
#include <cuda_runtime.h>
#include <cuda_bf16.h>
#include <stdint.h>

#define BB 4
#define SSQ 2048
#define DM 1024
#define NH 16
#define MR (BB*SSQ)

// ---------------------------------------------------------------------------
// Scratch: u32 = 2 bf16 (pair along contraction dim)
// ---------------------------------------------------------------------------
__device__ uint32_t g_wth[4*DM*512], g_wtl[4*DM*512];       // W^T split [n][kpair]
__device__ uint32_t g_xh[3u*MR*512], g_xl[3u*MR*512];       // split inputs
__device__ uint32_t g_Qh[MR*512], g_Ql[MR*512];
__device__ uint32_t g_Kh[MR*512], g_Kl[MR*512];
__device__ uint32_t g_Vh[MR*512], g_Vl[MR*512];
__device__ uint32_t g_Aoh[MR*512], g_Aol[MR*512];
__device__ float g_cm[BB*NH*SSQ], g_cr[BB*NH*SSQ];

// ---------------------------------------------------------------------------
// helpers
// ---------------------------------------------------------------------------
__device__ __forceinline__ void split2(float x, float y, uint32_t& hi, uint32_t& lo){
    __nv_bfloat16 hx = __float2bfloat16(x);
    __nv_bfloat16 hy = __float2bfloat16(y);
    float rx = x - __bfloat162float(hx);
    float ry = y - __bfloat162float(hy);
    __nv_bfloat162 h2 = __halves2bfloat162(hx, hy);
    __nv_bfloat162 l2 = __halves2bfloat162(__float2bfloat16(rx), __float2bfloat16(ry));
    hi = *reinterpret_cast<uint32_t*>(&h2);
    lo = *reinterpret_cast<uint32_t*>(&l2);
}

__device__ __forceinline__ void mma16(float* d,
    uint32_t a0, uint32_t a1, uint32_t a2, uint32_t a3, uint32_t b0, uint32_t b1)
{
    asm volatile(
        "mma.sync.aligned.m16n8k16.row.col.f32.bf16.bf16.f32 "
        "{%0,%1,%2,%3}, {%4,%5,%6,%7}, {%8,%9}, {%0,%1,%2,%3};\n"
        : "+f"(d[0]), "+f"(d[1]), "+f"(d[2]), "+f"(d[3])
        : "r"(a0), "r"(a1), "r"(a2), "r"(a3), "r"(b0), "r"(b1));
}

__device__ __forceinline__ uint32_t smem_u32(const void* p){
    uint32_t a;
    asm("{ .reg .u64 t; cvta.to.shared.u64 t, %1; cvt.u32.u64 %0, t; }" : "=r"(a) : "l"(p));
    return a;
}

__device__ __forceinline__ void ldsm4(uint32_t* r, uint32_t addr){
    asm volatile("ldmatrix.sync.aligned.m8n8.x4.shared.b16 {%0,%1,%2,%3}, [%4];"
        : "=r"(r[0]), "=r"(r[1]), "=r"(r[2]), "=r"(r[3]) : "r"(addr));
}
__device__ __forceinline__ void ldsm4t(uint32_t* r, uint32_t addr){
    asm volatile("ldmatrix.sync.aligned.m8n8.x4.trans.shared.b16 {%0,%1,%2,%3}, [%4];"
        : "=r"(r[0]), "=r"(r[1]), "=r"(r[2]), "=r"(r[3]) : "r"(addr));
}
__device__ __forceinline__ void ldsm2(uint32_t& r0, uint32_t& r1, uint32_t addr){
    asm volatile("ldmatrix.sync.aligned.m8n8.x2.shared.b16 {%0,%1}, [%2];"
        : "=r"(r0), "=r"(r1) : "r"(addr));
}

// swizzled u32 offset inside a [rows][16 u32] tile: chunk c (0..3) of 4 u32
__device__ __forceinline__ int swo(int r, int c){
    return (r << 4) + (((c ^ ((r >> 1) & 3))) << 2);
}

// ---------------------------------------------------------------------------
// prepass: split f32 -> bf16 hi/lo pairs
// ---------------------------------------------------------------------------
__global__ __launch_bounds__(256) void inprep(const float* __restrict__ in,
    uint32_t* __restrict__ oh, uint32_t* __restrict__ ol)
{
    size_t i = (size_t)blockIdx.x*256 + threadIdx.x;   // over MR*512
    float2 v = *(const float2*)(in + 2*i);
    uint32_t hh, ll; split2(v.x, v.y, hh, ll);
    oh[i] = hh; ol[i] = ll;
}

// W [k][n] f32 -> Wt split [n][512] u32 pairs along k
__global__ __launch_bounds__(256) void wprep(const float* __restrict__ W,
    uint32_t* __restrict__ oh, uint32_t* __restrict__ ol)
{
    __shared__ float t[64][33];
    const int k0 = blockIdx.x << 6, n0 = blockIdx.y << 5;
    const int tid = threadIdx.x;
#pragma unroll
    for (int i = 0; i < 8; i++){
        int v = i*256 + tid;
        int r = v >> 5, c = v & 31;
        t[r][c] = W[(size_t)(k0 + r)*DM + n0 + c];
    }
    __syncthreads();
    const int n = tid >> 3, pi = (tid & 7) << 2;
    uint4 H, L; uint32_t h, l;
    split2(t[2*pi][n],   t[2*pi+1][n], h, l); H.x = h; L.x = l;
    split2(t[2*pi+2][n], t[2*pi+3][n], h, l); H.y = h; L.y = l;
    split2(t[2*pi+4][n], t[2*pi+5][n], h, l); H.z = h; L.z = l;
    split2(t[2*pi+6][n], t[2*pi+7][n], h, l); H.w = h; L.w = l;
    size_t o = (size_t)(n0 + n)*512 + (k0 >> 1) + pi;
    *(uint4*)(oh + o) = H;
    *(uint4*)(ol + o) = L;
}

// ---------------------------------------------------------------------------
// proj_ms: C = A @ W + bias.  A,B pre-split u32 pairs along k. 3-pass mma.
// CTA 128x128, BK=32, 256 thr (8 warps 2x4, warp 64x32). ldmatrix frags.
// of != 0 -> f32 out; else split out (oh/ol).
// ---------------------------------------------------------------------------
__global__ __launch_bounds__(256) void proj_ms(
    const uint32_t* __restrict__ Ah, const uint32_t* __restrict__ Al,
    const uint32_t* __restrict__ Bh, const uint32_t* __restrict__ Bl,
    const float* __restrict__ bias,
    uint32_t* __restrict__ oh, uint32_t* __restrict__ ol,
    float* __restrict__ of)
{
    __shared__ uint32_t S[8192];   // Ah@0 Al@2048 Bh@4096 Bl@6144
    const int tid = threadIdx.x, lane = tid & 31, w = tid >> 5;
    const int wy = w >> 2, wx = w & 3;
    const int brow = blockIdx.y << 7, bcol = blockIdx.x << 7;
    const uint32_t sb = smem_u32(S);

    const int srow = tid >> 1, sh = tid & 1;
    const int sw = (srow >> 1) & 3;
    const int st0 = (srow << 4) + (((2*sh)   ^ sw) << 2);
    const int st1 = (srow << 4) + (((2*sh+1) ^ sw) << 2);

    const uint32_t* gA0 = Ah + (size_t)(brow + srow)*512 + sh*8;
    const uint32_t* gA1 = Al + (size_t)(brow + srow)*512 + sh*8;
    const uint32_t* gB0 = Bh + (size_t)(bcol + srow)*512 + sh*8;
    const uint32_t* gB1 = Bl + (size_t)(bcol + srow)*512 + sh*8;

    uint4 pa0 = *(const uint4*)gA0, pa1 = *(const uint4*)(gA0 + 4);
    uint4 pb0 = *(const uint4*)gA1, pb1 = *(const uint4*)(gA1 + 4);
    uint4 pc0 = *(const uint4*)gB0, pc1 = *(const uint4*)(gB0 + 4);
    uint4 pd0 = *(const uint4*)gB1, pd1 = *(const uint4*)(gB1 + 4);

    float acc[4][4][4];
#pragma unroll
    for (int mt = 0; mt < 4; mt++)
#pragma unroll
        for (int nt = 0; nt < 4; nt++)
#pragma unroll
            for (int j = 0; j < 4; j++) acc[mt][nt][j] = 0.f;

    for (int it = 0; it < 32; it++){
        *(uint4*)&S[st0]        = pa0; *(uint4*)&S[st1]        = pa1;
        *(uint4*)&S[2048 + st0] = pb0; *(uint4*)&S[2048 + st1] = pb1;
        *(uint4*)&S[4096 + st0] = pc0; *(uint4*)&S[4096 + st1] = pc1;
        *(uint4*)&S[6144 + st0] = pd0; *(uint4*)&S[6144 + st1] = pd1;
        __syncthreads();
        if (it < 31){
            int o = (it + 1) << 4;
            pa0 = *(const uint4*)(gA0 + o); pa1 = *(const uint4*)(gA0 + o + 4);
            pb0 = *(const uint4*)(gA1 + o); pb1 = *(const uint4*)(gA1 + o + 4);
            pc0 = *(const uint4*)(gB0 + o); pc1 = *(const uint4*)(gB0 + o + 4);
            pd0 = *(const uint4*)(gB1 + o); pd1 = *(const uint4*)(gB1 + o + 4);
        }
        // B fragments: x4 covers both kc
        uint32_t bhv[4][4], blv[4][4];
#pragma unroll
        for (int nt = 0; nt < 4; nt++){
            int rB = wx*32 + nt*8 + (lane & 7);
            int cB = lane >> 3;
            uint32_t ad = sb + 4*(4096 + swo(rB, cB));
            ldsm4(bhv[nt], ad);
            ldsm4(blv[nt], ad + 2048*4);
        }
#pragma unroll
        for (int kc = 0; kc < 2; kc++){
#pragma unroll
            for (int mt = 0; mt < 4; mt++){
                uint32_t ahv[4], alv[4];
                int rA = wy*64 + mt*16 + (lane & 15);
                int cA = 2*kc + (lane >> 4);
                uint32_t ad = sb + 4*swo(rA, cA);
                ldsm4(ahv, ad);
                ldsm4(alv, ad + 2048*4);
#pragma unroll
                for (int nt = 0; nt < 4; nt++){
                    mma16(acc[mt][nt], ahv[0],ahv[1],ahv[2],ahv[3], bhv[nt][2*kc], bhv[nt][2*kc+1]);
                    mma16(acc[mt][nt], alv[0],alv[1],alv[2],alv[3], bhv[nt][2*kc], bhv[nt][2*kc+1]);
                    mma16(acc[mt][nt], ahv[0],ahv[1],ahv[2],ahv[3], blv[nt][2*kc], blv[nt][2*kc+1]);
                }
            }
        }
        __syncthreads();
    }

#pragma unroll
    for (int mt = 0; mt < 4; mt++)
#pragma unroll
        for (int nt = 0; nt < 4; nt++){
            int row = brow + wy*64 + mt*16 + (lane >> 2);
            int col = bcol + wx*32 + nt*8 + ((lane & 3) << 1);
            float b0 = bias[col], b1 = bias[col+1];
            float v0 = acc[mt][nt][0] + b0, v1 = acc[mt][nt][1] + b1;
            float v2 = acc[mt][nt][2] + b0, v3 = acc[mt][nt][3] + b1;
            if (of){
                *(float2*)(of + (size_t)row*DM + col)     = make_float2(v0, v1);
                *(float2*)(of + (size_t)(row+8)*DM + col) = make_float2(v2, v3);
            } else {
                uint32_t hh, ll;
                split2(v0, v1, hh, ll);
                oh[(size_t)row*512 + (col>>1)] = hh; ol[(size_t)row*512 + (col>>1)] = ll;
                split2(v2, v3, hh, ll);
                oh[(size_t)(row+8)*512 + (col>>1)] = hh; ol[(size_t)(row+8)*512 + (col>>1)] = ll;
            }
        }
}

// ---------------------------------------------------------------------------
// colstats: per-key-column max/sumexp over all queries (softmax over q axis).
// grid (64 bh, 16 key-tiles); K frags direct from global; Q via smem tiles.
// ---------------------------------------------------------------------------
__global__ __launch_bounds__(256) void colstats(float* __restrict__ cm,
                                                float* __restrict__ cr)
{
    __shared__ uint32_t S[8192];   // [arr hi/lo][dblk][128][16]
    const int tid = threadIdx.x, lane = tid & 31, w = tid >> 5;
    const int bh = blockIdx.x, kt0 = blockIdx.y << 7;
    const int b = bh >> 4, h = bh & 15;
    const uint32_t sb = smem_u32(S);

    // K fragments resident (direct global)
    uint2 kbh[2][4], kbl[2][4];
#pragma unroll
    for (int nt2 = 0; nt2 < 2; nt2++)
#pragma unroll
        for (int kc = 0; kc < 4; kc++){
            int key = kt0 + w*16 + nt2*8 + (lane >> 2);
            size_t o = (size_t)(b*SSQ + key)*512 + h*32 + kc*8 + (lane & 3);
            kbh[nt2][kc] = make_uint2(g_Kh[o], g_Kh[o+4]);
            kbl[nt2][kc] = make_uint2(g_Kl[o], g_Kl[o+4]);
        }

    const int srow = tid >> 1, sh = tid & 1;
    const int sw = (srow >> 1) & 3;
    const int st0 = (srow << 4) + (((2*sh)   ^ sw) << 2);
    const int st1 = (srow << 4) + (((2*sh+1) ^ sw) << 2);

    float mst[4] = {-1e30f, -1e30f, -1e30f, -1e30f};
    float zst[4] = {0.f, 0.f, 0.f, 0.f};

    for (int qt = 0; qt < 16; qt++){
#pragma unroll
        for (int arr = 0; arr < 2; arr++)
#pragma unroll
            for (int dblk = 0; dblk < 2; dblk++){
                const uint32_t* src = (arr ? g_Ql : g_Qh)
                    + (size_t)(b*SSQ + qt*128 + srow)*512 + h*32 + dblk*16 + sh*8;
                int base = arr*4096 + dblk*2048;
                *(uint4*)&S[base + st0] = *(const uint4*)src;
                *(uint4*)&S[base + st1] = *(const uint4*)(src + 4);
            }
        __syncthreads();

        float acc[8][2][4];
#pragma unroll
        for (int mt = 0; mt < 8; mt++)
#pragma unroll
            for (int nt2 = 0; nt2 < 2; nt2++)
#pragma unroll
                for (int j = 0; j < 4; j++) acc[mt][nt2][j] = 0.f;

#pragma unroll
        for (int mt = 0; mt < 8; mt++)
#pragma unroll
            for (int kcd = 0; kcd < 4; kcd++){
                int dblk = kcd >> 1, kc = kcd & 1;
                uint32_t qh[4], ql[4];
                int rA = mt*16 + (lane & 15);
                int cA = 2*kc + (lane >> 4);
                uint32_t ad = sb + 4*(dblk*2048 + swo(rA, cA));
                ldsm4(qh, ad);
                ldsm4(ql, ad + 4096*4);
#pragma unroll
                for (int nt2 = 0; nt2 < 2; nt2++){
                    mma16(acc[mt][nt2], qh[0],qh[1],qh[2],qh[3], kbh[nt2][kcd].x, kbh[nt2][kcd].y);
                    mma16(acc[mt][nt2], ql[0],ql[1],ql[2],ql[3], kbh[nt2][kcd].x, kbh[nt2][kcd].y);
                    mma16(acc[mt][nt2], qh[0],qh[1],qh[2],qh[3], kbl[nt2][kcd].x, kbl[nt2][kcd].y);
                }
            }

#pragma unroll
        for (int nt2 = 0; nt2 < 2; nt2++)
#pragma unroll
            for (int hh = 0; hh < 2; hh++){
                int si = nt2*2 + hh;
                float tmax = -1e30f;
#pragma unroll
                for (int mt = 0; mt < 8; mt++)
                    tmax = fmaxf(tmax, fmaxf(acc[mt][nt2][hh], acc[mt][nt2][hh+2]));
                tmax = fmaxf(tmax, __shfl_xor_sync(0xffffffffu, tmax, 4));
                tmax = fmaxf(tmax, __shfl_xor_sync(0xffffffffu, tmax, 8));
                tmax = fmaxf(tmax, __shfl_xor_sync(0xffffffffu, tmax, 16));
                float mn = fmaxf(mst[si], tmax);
                float ts = 0.f;
#pragma unroll
                for (int mt = 0; mt < 8; mt++)
                    ts += __expf(acc[mt][nt2][hh] - mn) + __expf(acc[mt][nt2][hh+2] - mn);
                ts += __shfl_xor_sync(0xffffffffu, ts, 4);
                ts += __shfl_xor_sync(0xffffffffu, ts, 8);
                ts += __shfl_xor_sync(0xffffffffu, ts, 16);
                zst[si] = zst[si] * __expf(mst[si] - mn) + ts;
                mst[si] = mn;
            }
        __syncthreads();
    }

    if (lane < 4){
#pragma unroll
        for (int nt2 = 0; nt2 < 2; nt2++)
#pragma unroll
            for (int hh = 0; hh < 2; hh++){
                int col = kt0 + w*16 + nt2*8 + lane*2 + hh;
                cm[(size_t)bh*SSQ + col] = mst[nt2*2 + hh];
                cr[(size_t)bh*SSQ + col] = 1.0f / (8.0f * zst[nt2*2 + hh]);
            }
    }
}

// ---------------------------------------------------------------------------
// attn: fused QK^T recompute + exp-scale + E@V. E in registers; V via
// ldmatrix.trans (no transpose staging). Writes split Ao.
// ---------------------------------------------------------------------------
#define AT_U32   (8192 + 4*2056 + 128)
#define AT_BYTES (AT_U32*4)

__global__ __launch_bounds__(256) void attn(const float* __restrict__ cm,
                                            const float* __restrict__ cr)
{
    extern __shared__ uint32_t su[];
    const uint32_t sb = smem_u32(su);
    const int tid = threadIdx.x, lane = tid & 31, w = tid >> 5;
    const int g = lane >> 2, t = lane & 3;
    const int bh = blockIdx.x, qt0 = blockIdx.y << 7;
    const int b = bh >> 4, h = bh & 15;
    float* mS = (float*)(su + 8192 + 4*2056);
    float* rS = mS + 64;

    // stage Q resident
    {
        const int srow = tid >> 1, sh = tid & 1;
        const int sw = (srow >> 1) & 3;
        const int st0 = (srow << 4) + (((2*sh)   ^ sw) << 2);
        const int st1 = (srow << 4) + (((2*sh+1) ^ sw) << 2);
#pragma unroll
        for (int arr = 0; arr < 2; arr++)
#pragma unroll
            for (int dblk = 0; dblk < 2; dblk++){
                const uint32_t* src = (arr ? g_Ql : g_Qh)
                    + (size_t)(b*SSQ + qt0 + srow)*512 + h*32 + dblk*16 + sh*8;
                int base = arr*4096 + dblk*2048;
                *(uint4*)&su[base + st0] = *(const uint4*)src;
                *(uint4*)&su[base + st1] = *(const uint4*)(src + 4);
            }
    }

    const int krow = tid >> 2, kdb = (tid >> 1) & 1, khh = tid & 1;
    const int ksw = (krow >> 1) & 3;
    const int kst0 = (krow << 4) + (((2*khh)   ^ ksw) << 2);
    const int kst1 = (krow << 4) + (((2*khh+1) ^ ksw) << 2);

    float accO[8][4];
#pragma unroll
    for (int nt = 0; nt < 8; nt++)
#pragma unroll
        for (int j = 0; j < 4; j++) accO[nt][j] = 0.f;

    for (int kt = 0; kt < 32; kt++){
        const int k0 = kt << 6;
        __syncthreads();
        {
            size_t go = (size_t)(b*SSQ + k0 + krow)*512 + h*32 + kdb*16 + khh*8;
            const uint32_t* srcs[4] = { g_Kh + go, g_Kl + go, g_Vh + go, g_Vl + go };
#pragma unroll
            for (int arr = 0; arr < 4; arr++){
                int base = 8192 + arr*2056 + kdb*1028;
                *(uint4*)&su[base + kst0] = *(const uint4*)srcs[arr];
                *(uint4*)&su[base + kst1] = *(const uint4*)(srcs[arr] + 4);
            }
        }
        if (tid < 64){
            mS[tid] = cm[(size_t)bh*SSQ + k0 + tid];
            rS[tid] = cr[(size_t)bh*SSQ + k0 + tid];
        }
        __syncthreads();

        // S = Q K^T  (warp's 16 q rows x 64 keys)
        float accs[8][4];
#pragma unroll
        for (int nt = 0; nt < 8; nt++)
#pragma unroll
            for (int j = 0; j < 4; j++) accs[nt][j] = 0.f;

#pragma unroll
        for (int kcd = 0; kcd < 4; kcd++){
            int dblk = kcd >> 1, kc = kcd & 1;
            uint32_t qh[4], ql[4];
            uint32_t aq = sb + 4*(dblk*2048 + swo(w*16 + (lane & 15), 2*kc + (lane >> 4)));
            ldsm4(qh, aq);
            ldsm4(ql, aq + 4096*4);
            int rK = (lane & 7);
            int cK = 2*kc + ((lane >> 3) & 1);
#pragma unroll
            for (int nt = 0; nt < 8; nt++){
                uint32_t ak = sb + 4*(8192 + dblk*1028 + swo(nt*8 + rK, cK));
                uint32_t k0h, k1h, k0l, k1l;
                ldsm2(k0h, k1h, ak);
                ldsm2(k0l, k1l, ak + 2056*4);
                mma16(accs[nt], qh[0],qh[1],qh[2],qh[3], k0h, k1h);
                mma16(accs[nt], ql[0],ql[1],ql[2],ql[3], k0h, k1h);
                mma16(accs[nt], qh[0],qh[1],qh[2],qh[3], k0l, k1l);
            }
        }

        // E = exp(s - m[k]) * r[k]; in-register repack C-frag -> A-frag
        uint32_t EH[4][4], EL[4][4];
#pragma unroll
        for (int nt = 0; nt < 8; nt++){
            int kcp = nt >> 1, rb = (nt & 1) << 1;
            int c0 = nt*8 + t*2, c1 = c0 + 1;
            float m0 = mS[c0], m1 = mS[c1], r0 = rS[c0], r1 = rS[c1];
            float e00 = __expf(accs[nt][0] - m0) * r0;
            float e01 = __expf(accs[nt][1] - m1) * r1;
            float e10 = __expf(accs[nt][2] - m0) * r0;
            float e11 = __expf(accs[nt][3] - m1) * r1;
            uint32_t hh, ll;
            split2(e00, e01, hh, ll); EH[kcp][rb]   = hh; EL[kcp][rb]   = ll;
            split2(e10, e11, hh, ll); EH[kcp][rb+1] = hh; EL[kcp][rb+1] = ll;
        }

        // O += E @ V  (V frags via ldmatrix.trans; pairs along key)
#pragma unroll
        for (int ntd = 0; ntd < 8; ntd++){
            int dbd = ntd >> 2, ch = ntd & 3;
#pragma unroll
            for (int kcp = 0; kcp < 2; kcp++){
                uint32_t vh4[4], vl4[4];
                uint32_t av = sb + 4*(8192 + 2*2056 + dbd*1028 + swo(kcp*32 + lane, ch));
                ldsm4t(vh4, av);
                ldsm4t(vl4, av + 2056*4);
                int ka = 2*kcp, kb = 2*kcp + 1;
                mma16(accO[ntd], EH[ka][0],EH[ka][1],EH[ka][2],EH[ka][3], vh4[0], vh4[1]);
                mma16(accO[ntd], EL[ka][0],EL[ka][1],EL[ka][2],EL[ka][3], vh4[0], vh4[1]);
                mma16(accO[ntd], EH[ka][0],EH[ka][1],EH[ka][2],EH[ka][3], vl4[0], vl4[1]);
                mma16(accO[ntd], EH[kb][0],EH[kb][1],EH[kb][2],EH[kb][3], vh4[2], vh4[3]);
                mma16(accO[ntd], EL[kb][0],EL[kb][1],EL[kb][2],EL[kb][3], vh4[2], vh4[3]);
                mma16(accO[ntd], EH[kb][0],EH[kb][1],EH[kb][2],EH[kb][3], vl4[2], vl4[3]);
            }
        }
    }

    // write split Ao
    const int row = qt0 + w*16 + g;
#pragma unroll
    for (int nt = 0; nt < 8; nt++){
        int col = nt*8 + t*2;
        uint32_t hh, ll;
        split2(accO[nt][0], accO[nt][1], hh, ll);
        g_Aoh[(size_t)(b*SSQ + row)*512 + h*32 + (col>>1)] = hh;
        g_Aol[(size_t)(b*SSQ + row)*512 + h*32 + (col>>1)] = ll;
        split2(accO[nt][2], accO[nt][3], hh, ll);
        g_Aoh[(size_t)(b*SSQ + row + 8)*512 + h*32 + (col>>1)] = hh;
        g_Aol[(size_t)(b*SSQ + row + 8)*512 + h*32 + (col>>1)] = ll;
    }
}

// ---------------------------------------------------------------------------
// Launch
// ---------------------------------------------------------------------------
extern "C" void kernel_launch(void* const* d_in, const int* in_sizes, int n_in,
                              void* d_out, int out_size)
{
    const float* qin = (const float*)d_in[0];
    const float* kin = (const float*)d_in[1];
    const float* vin = (const float*)d_in[2];
    const float* Wq  = (const float*)d_in[3];
    const float* bq  = (const float*)d_in[4];
    const float* Wk  = (const float*)d_in[5];
    const float* bk  = (const float*)d_in[6];
    const float* Wv  = (const float*)d_in[7];
    const float* bv  = (const float*)d_in[8];
    const float* Wo  = (const float*)d_in[9];
    const float* bo  = (const float*)d_in[10];

    uint32_t *wth, *wtl, *xh, *xl, *Qh, *Ql, *Kh, *Kl, *Vh, *Vl, *Aoh, *Aol;
    float *cm, *cr;
    cudaGetSymbolAddress((void**)&wth, g_wth);
    cudaGetSymbolAddress((void**)&wtl, g_wtl);
    cudaGetSymbolAddress((void**)&xh,  g_xh);
    cudaGetSymbolAddress((void**)&xl,  g_xl);
    cudaGetSymbolAddress((void**)&Qh,  g_Qh);
    cudaGetSymbolAddress((void**)&Ql,  g_Ql);
    cudaGetSymbolAddress((void**)&Kh,  g_Kh);
    cudaGetSymbolAddress((void**)&Kl,  g_Kl);
    cudaGetSymbolAddress((void**)&Vh,  g_Vh);
    cudaGetSymbolAddress((void**)&Vl,  g_Vl);
    cudaGetSymbolAddress((void**)&Aoh, g_Aoh);
    cudaGetSymbolAddress((void**)&Aol, g_Aol);
    cudaGetSymbolAddress((void**)&cm,  g_cm);
    cudaGetSymbolAddress((void**)&cr,  g_cr);

    cudaFuncSetAttribute(attn, cudaFuncAttributeMaxDynamicSharedMemorySize, AT_BYTES);

    const size_t XS = (size_t)MR*512;
    const size_t WS = (size_t)DM*512;

    inprep<<<MR*512/256, 256>>>(qin, xh + 0*XS, xl + 0*XS);
    inprep<<<MR*512/256, 256>>>(kin, xh + 1*XS, xl + 1*XS);
    inprep<<<MR*512/256, 256>>>(vin, xh + 2*XS, xl + 2*XS);

    dim3 gW(16, 32);
    wprep<<<gW, 256>>>(Wq, wth + 0*WS, wtl + 0*WS);
    wprep<<<gW, 256>>>(Wk, wth + 1*WS, wtl + 1*WS);
    wprep<<<gW, 256>>>(Wv, wth + 2*WS, wtl + 2*WS);
    wprep<<<gW, 256>>>(Wo, wth + 3*WS, wtl + 3*WS);

    dim3 gP(DM/128, MR/128);   // (8, 64)
    proj_ms<<<gP, 256>>>(xh + 0*XS, xl + 0*XS, wth + 0*WS, wtl + 0*WS, bq, Qh, Ql, nullptr);
    proj_ms<<<gP, 256>>>(xh + 1*XS, xl + 1*XS, wth + 1*WS, wtl + 1*WS, bk, Kh, Kl, nullptr);
    proj_ms<<<gP, 256>>>(xh + 2*XS, xl + 2*XS, wth + 2*WS, wtl + 2*WS, bv, Vh, Vl, nullptr);

    colstats<<<dim3(BB*NH, SSQ/128), 256>>>(cm, cr);

    attn<<<dim3(BB*NH, SSQ/128), 256, AT_BYTES>>>(cm, cr);

    proj_ms<<<gP, 256>>>(Aoh, Aol, wth + 3*WS, wtl + 3*WS, bo, nullptr, nullptr, (float*)d_out);
}

// round 7
// speedup vs baseline: 1.6265x; 1.0025x over previous
#include <cuda_runtime.h>
#include <cuda_bf16.h>
#include <stdint.h>

#define BB 4
#define SSQ 2048
#define DM 1024
#define NH 16
#define MR (BB*SSQ)

// ---------------------------------------------------------------------------
// Scratch: u32 = 2 bf16 (pair along contraction dim)
// ---------------------------------------------------------------------------
__device__ uint32_t g_wth[4*DM*512], g_wtl[4*DM*512];       // W^T split [n][kpair]
__device__ uint32_t g_xh[3u*MR*512], g_xl[3u*MR*512];       // split inputs
__device__ uint32_t g_Qh[MR*512], g_Ql[MR*512];
__device__ uint32_t g_Kh[MR*512], g_Kl[MR*512];
__device__ uint32_t g_Vh[MR*512], g_Vl[MR*512];
__device__ uint32_t g_Aoh[MR*512], g_Aol[MR*512];
__device__ float g_cm[BB*NH*SSQ], g_cr[BB*NH*SSQ];

// ---------------------------------------------------------------------------
// helpers
// ---------------------------------------------------------------------------
__device__ __forceinline__ void split2(float x, float y, uint32_t& hi, uint32_t& lo){
    __nv_bfloat16 hx = __float2bfloat16(x);
    __nv_bfloat16 hy = __float2bfloat16(y);
    float rx = x - __bfloat162float(hx);
    float ry = y - __bfloat162float(hy);
    __nv_bfloat162 h2 = __halves2bfloat162(hx, hy);
    __nv_bfloat162 l2 = __halves2bfloat162(__float2bfloat16(rx), __float2bfloat16(ry));
    hi = *reinterpret_cast<uint32_t*>(&h2);
    lo = *reinterpret_cast<uint32_t*>(&l2);
}

__device__ __forceinline__ void mma16(float* d,
    uint32_t a0, uint32_t a1, uint32_t a2, uint32_t a3, uint32_t b0, uint32_t b1)
{
    asm volatile(
        "mma.sync.aligned.m16n8k16.row.col.f32.bf16.bf16.f32 "
        "{%0,%1,%2,%3}, {%4,%5,%6,%7}, {%8,%9}, {%0,%1,%2,%3};\n"
        : "+f"(d[0]), "+f"(d[1]), "+f"(d[2]), "+f"(d[3])
        : "r"(a0), "r"(a1), "r"(a2), "r"(a3), "r"(b0), "r"(b1));
}

__device__ __forceinline__ uint32_t smem_u32(const void* p){
    uint32_t a;
    asm("{ .reg .u64 t; cvta.to.shared.u64 t, %1; cvt.u32.u64 %0, t; }" : "=r"(a) : "l"(p));
    return a;
}

__device__ __forceinline__ void ldsm4(uint32_t* r, uint32_t addr){
    asm volatile("ldmatrix.sync.aligned.m8n8.x4.shared.b16 {%0,%1,%2,%3}, [%4];"
        : "=r"(r[0]), "=r"(r[1]), "=r"(r[2]), "=r"(r[3]) : "r"(addr));
}
__device__ __forceinline__ void ldsm4t(uint32_t* r, uint32_t addr){
    asm volatile("ldmatrix.sync.aligned.m8n8.x4.trans.shared.b16 {%0,%1,%2,%3}, [%4];"
        : "=r"(r[0]), "=r"(r[1]), "=r"(r[2]), "=r"(r[3]) : "r"(addr));
}
__device__ __forceinline__ void ldsm2(uint32_t& r0, uint32_t& r1, uint32_t addr){
    asm volatile("ldmatrix.sync.aligned.m8n8.x2.shared.b16 {%0,%1}, [%2];"
        : "=r"(r0), "=r"(r1) : "r"(addr));
}

__device__ __forceinline__ void cpa16(uint32_t dst, const void* src){
    asm volatile("cp.async.cg.shared.global [%0], [%1], 16;\n" :: "r"(dst), "l"(src));
}
#define CP_COMMIT asm volatile("cp.async.commit_group;\n" ::: "memory")
#define CP_WAIT0  asm volatile("cp.async.wait_group 0;\n" ::: "memory")

// swizzled u32 offset inside a [rows][16 u32] tile: chunk c (0..3) of 4 u32
__device__ __forceinline__ int swo(int r, int c){
    return (r << 4) + (((c ^ ((r >> 1) & 3))) << 2);
}

// ---------------------------------------------------------------------------
// prepass: split f32 -> bf16 hi/lo pairs
// ---------------------------------------------------------------------------
__global__ __launch_bounds__(256) void inprep(const float* __restrict__ in,
    uint32_t* __restrict__ oh, uint32_t* __restrict__ ol)
{
    size_t i = (size_t)blockIdx.x*256 + threadIdx.x;
    float2 v = *(const float2*)(in + 2*i);
    uint32_t hh, ll; split2(v.x, v.y, hh, ll);
    oh[i] = hh; ol[i] = ll;
}

// W [k][n] f32 -> Wt split [n][512] u32 pairs along k
__global__ __launch_bounds__(256) void wprep(const float* __restrict__ W,
    uint32_t* __restrict__ oh, uint32_t* __restrict__ ol)
{
    __shared__ float t[64][33];
    const int k0 = blockIdx.x << 6, n0 = blockIdx.y << 5;
    const int tid = threadIdx.x;
#pragma unroll
    for (int i = 0; i < 8; i++){
        int v = i*256 + tid;
        int r = v >> 5, c = v & 31;
        t[r][c] = W[(size_t)(k0 + r)*DM + n0 + c];
    }
    __syncthreads();
    const int n = tid >> 3, pi = (tid & 7) << 2;
    uint4 H, L; uint32_t h, l;
    split2(t[2*pi][n],   t[2*pi+1][n], h, l); H.x = h; L.x = l;
    split2(t[2*pi+2][n], t[2*pi+3][n], h, l); H.y = h; L.y = l;
    split2(t[2*pi+4][n], t[2*pi+5][n], h, l); H.z = h; L.z = l;
    split2(t[2*pi+6][n], t[2*pi+7][n], h, l); H.w = h; L.w = l;
    size_t o = (size_t)(n0 + n)*512 + (k0 >> 1) + pi;
    *(uint4*)(oh + o) = H;
    *(uint4*)(ol + o) = L;
}

// ---------------------------------------------------------------------------
// proj_ms: C = A @ W + bias. 3-pass split mma, cp.async double-buffered.
// CTA 128x128, BK=32, 256 thr (8 warps 2x4, warp 64x32).
// ---------------------------------------------------------------------------
__global__ __launch_bounds__(256) void proj_ms(
    const uint32_t* __restrict__ Ah, const uint32_t* __restrict__ Al,
    const uint32_t* __restrict__ Bh, const uint32_t* __restrict__ Bl,
    const float* __restrict__ bias,
    uint32_t* __restrict__ oh, uint32_t* __restrict__ ol,
    float* __restrict__ of)
{
    __shared__ uint32_t S[16384];   // 2 buffers x (Ah@0 Al@2048 Bh@4096 Bl@6144)
    const int tid = threadIdx.x, lane = tid & 31, w = tid >> 5;
    const int wy = w >> 2, wx = w & 3;
    const int brow = blockIdx.y << 7, bcol = blockIdx.x << 7;
    const uint32_t sb = smem_u32(S);

    const int srow = tid >> 1, sh = tid & 1;
    const int sw = (srow >> 1) & 3;
    const int st0 = (srow << 4) + (((2*sh)   ^ sw) << 2);
    const int st1 = (srow << 4) + (((2*sh+1) ^ sw) << 2);

    const uint32_t* gA0 = Ah + (size_t)(brow + srow)*512 + sh*8;
    const uint32_t* gA1 = Al + (size_t)(brow + srow)*512 + sh*8;
    const uint32_t* gB0 = Bh + (size_t)(bcol + srow)*512 + sh*8;
    const uint32_t* gB1 = Bl + (size_t)(bcol + srow)*512 + sh*8;

#define PSTAGE(s, B) do { \
        int o = (s) << 4; \
        cpa16(sb + 4*((B) + st0),        gA0 + o); cpa16(sb + 4*((B) + st1),        gA0 + o + 4); \
        cpa16(sb + 4*((B) + 2048 + st0), gA1 + o); cpa16(sb + 4*((B) + 2048 + st1), gA1 + o + 4); \
        cpa16(sb + 4*((B) + 4096 + st0), gB0 + o); cpa16(sb + 4*((B) + 4096 + st1), gB0 + o + 4); \
        cpa16(sb + 4*((B) + 6144 + st0), gB1 + o); cpa16(sb + 4*((B) + 6144 + st1), gB1 + o + 4); \
        CP_COMMIT; } while(0)

    float acc[4][4][4];
#pragma unroll
    for (int mt = 0; mt < 4; mt++)
#pragma unroll
        for (int nt = 0; nt < 4; nt++)
#pragma unroll
            for (int j = 0; j < 4; j++) acc[mt][nt][j] = 0.f;

    PSTAGE(0, 0);

    for (int it = 0; it < 32; it++){
        const int B = (it & 1) << 13;
        CP_WAIT0;
        __syncthreads();
        if (it < 31) PSTAGE(it + 1, ((it + 1) & 1) << 13);

        uint32_t bhv[4][4], blv[4][4];
#pragma unroll
        for (int nt = 0; nt < 4; nt++){
            int rB = wx*32 + nt*8 + (lane & 7);
            int cB = lane >> 3;
            uint32_t ad = sb + 4*(B + 4096 + swo(rB, cB));
            ldsm4(bhv[nt], ad);
            ldsm4(blv[nt], ad + 2048*4);
        }
#pragma unroll
        for (int kc = 0; kc < 2; kc++){
#pragma unroll
            for (int mt = 0; mt < 4; mt++){
                uint32_t ahv[4], alv[4];
                int rA = wy*64 + mt*16 + (lane & 15);
                int cA = 2*kc + (lane >> 4);
                uint32_t ad = sb + 4*(B + swo(rA, cA));
                ldsm4(ahv, ad);
                ldsm4(alv, ad + 2048*4);
#pragma unroll
                for (int nt = 0; nt < 4; nt++){
                    mma16(acc[mt][nt], ahv[0],ahv[1],ahv[2],ahv[3], bhv[nt][2*kc], bhv[nt][2*kc+1]);
                    mma16(acc[mt][nt], alv[0],alv[1],alv[2],alv[3], bhv[nt][2*kc], bhv[nt][2*kc+1]);
                    mma16(acc[mt][nt], ahv[0],ahv[1],ahv[2],ahv[3], blv[nt][2*kc], blv[nt][2*kc+1]);
                }
            }
        }
    }
#undef PSTAGE

#pragma unroll
    for (int mt = 0; mt < 4; mt++)
#pragma unroll
        for (int nt = 0; nt < 4; nt++){
            int row = brow + wy*64 + mt*16 + (lane >> 2);
            int col = bcol + wx*32 + nt*8 + ((lane & 3) << 1);
            float b0 = bias[col], b1 = bias[col+1];
            float v0 = acc[mt][nt][0] + b0, v1 = acc[mt][nt][1] + b1;
            float v2 = acc[mt][nt][2] + b0, v3 = acc[mt][nt][3] + b1;
            if (of){
                *(float2*)(of + (size_t)row*DM + col)     = make_float2(v0, v1);
                *(float2*)(of + (size_t)(row+8)*DM + col) = make_float2(v2, v3);
            } else {
                uint32_t hh, ll;
                split2(v0, v1, hh, ll);
                oh[(size_t)row*512 + (col>>1)] = hh; ol[(size_t)row*512 + (col>>1)] = ll;
                split2(v2, v3, hh, ll);
                oh[(size_t)(row+8)*512 + (col>>1)] = hh; ol[(size_t)(row+8)*512 + (col>>1)] = ll;
            }
        }
}

// ---------------------------------------------------------------------------
// colstats: per-key-column max/sumexp over all queries (softmax over q axis).
// K frags direct from global; Q via cp.async double-buffered smem tiles.
// ---------------------------------------------------------------------------
__global__ __launch_bounds__(256) void colstats(float* __restrict__ cm,
                                                float* __restrict__ cr)
{
    __shared__ uint32_t S[16384];   // 2 buffers x [arr hi/lo][dblk][128][16]
    const int tid = threadIdx.x, lane = tid & 31, w = tid >> 5;
    const int bh = blockIdx.x, kt0 = blockIdx.y << 7;
    const int b = bh >> 4, h = bh & 15;
    const uint32_t sb = smem_u32(S);

    uint2 kbh[2][4], kbl[2][4];
#pragma unroll
    for (int nt2 = 0; nt2 < 2; nt2++)
#pragma unroll
        for (int kc = 0; kc < 4; kc++){
            int key = kt0 + w*16 + nt2*8 + (lane >> 2);
            size_t o = (size_t)(b*SSQ + key)*512 + h*32 + kc*8 + (lane & 3);
            kbh[nt2][kc] = make_uint2(g_Kh[o], g_Kh[o+4]);
            kbl[nt2][kc] = make_uint2(g_Kl[o], g_Kl[o+4]);
        }

    const int srow = tid >> 1, sh = tid & 1;
    const int sw = (srow >> 1) & 3;
    const int st0 = (srow << 4) + (((2*sh)   ^ sw) << 2);
    const int st1 = (srow << 4) + (((2*sh+1) ^ sw) << 2);

#define QSTAGE(qt, B) do { \
        _Pragma("unroll") \
        for (int arr = 0; arr < 2; arr++){ \
            _Pragma("unroll") \
            for (int dblk = 0; dblk < 2; dblk++){ \
                const uint32_t* src = (arr ? g_Ql : g_Qh) \
                    + (size_t)(b*SSQ + (qt)*128 + srow)*512 + h*32 + dblk*16 + sh*8; \
                int base = (B) + arr*4096 + dblk*2048; \
                cpa16(sb + 4*(base + st0), src); \
                cpa16(sb + 4*(base + st1), src + 4); \
            } \
        } \
        CP_COMMIT; } while(0)

    float mst[4] = {-1e30f, -1e30f, -1e30f, -1e30f};
    float zst[4] = {0.f, 0.f, 0.f, 0.f};

    QSTAGE(0, 0);

    for (int qt = 0; qt < 16; qt++){
        const int B = (qt & 1) << 13;
        CP_WAIT0;
        __syncthreads();
        if (qt < 15) QSTAGE(qt + 1, ((qt + 1) & 1) << 13);

        float acc[8][2][4];
#pragma unroll
        for (int mt = 0; mt < 8; mt++)
#pragma unroll
            for (int nt2 = 0; nt2 < 2; nt2++)
#pragma unroll
                for (int j = 0; j < 4; j++) acc[mt][nt2][j] = 0.f;

#pragma unroll
        for (int mt = 0; mt < 8; mt++)
#pragma unroll
            for (int kcd = 0; kcd < 4; kcd++){
                int dblk = kcd >> 1, kc = kcd & 1;
                uint32_t qh[4], ql[4];
                int rA = mt*16 + (lane & 15);
                int cA = 2*kc + (lane >> 4);
                uint32_t ad = sb + 4*(B + dblk*2048 + swo(rA, cA));
                ldsm4(qh, ad);
                ldsm4(ql, ad + 4096*4);
#pragma unroll
                for (int nt2 = 0; nt2 < 2; nt2++){
                    mma16(acc[mt][nt2], qh[0],qh[1],qh[2],qh[3], kbh[nt2][kcd].x, kbh[nt2][kcd].y);
                    mma16(acc[mt][nt2], ql[0],ql[1],ql[2],ql[3], kbh[nt2][kcd].x, kbh[nt2][kcd].y);
                    mma16(acc[mt][nt2], qh[0],qh[1],qh[2],qh[3], kbl[nt2][kcd].x, kbl[nt2][kcd].y);
                }
            }

#pragma unroll
        for (int nt2 = 0; nt2 < 2; nt2++)
#pragma unroll
            for (int hh = 0; hh < 2; hh++){
                int si = nt2*2 + hh;
                float tmax = -1e30f;
#pragma unroll
                for (int mt = 0; mt < 8; mt++)
                    tmax = fmaxf(tmax, fmaxf(acc[mt][nt2][hh], acc[mt][nt2][hh+2]));
                tmax = fmaxf(tmax, __shfl_xor_sync(0xffffffffu, tmax, 4));
                tmax = fmaxf(tmax, __shfl_xor_sync(0xffffffffu, tmax, 8));
                tmax = fmaxf(tmax, __shfl_xor_sync(0xffffffffu, tmax, 16));
                float mn = fmaxf(mst[si], tmax);
                float ts = 0.f;
#pragma unroll
                for (int mt = 0; mt < 8; mt++)
                    ts += __expf(acc[mt][nt2][hh] - mn) + __expf(acc[mt][nt2][hh+2] - mn);
                ts += __shfl_xor_sync(0xffffffffu, ts, 4);
                ts += __shfl_xor_sync(0xffffffffu, ts, 8);
                ts += __shfl_xor_sync(0xffffffffu, ts, 16);
                zst[si] = zst[si] * __expf(mst[si] - mn) + ts;
                mst[si] = mn;
            }
    }
#undef QSTAGE

    if (lane < 4){
#pragma unroll
        for (int nt2 = 0; nt2 < 2; nt2++)
#pragma unroll
            for (int hh = 0; hh < 2; hh++){
                int col = kt0 + w*16 + nt2*8 + lane*2 + hh;
                cm[(size_t)bh*SSQ + col] = mst[nt2*2 + hh];
                cr[(size_t)bh*SSQ + col] = 1.0f / (8.0f * zst[nt2*2 + hh]);
            }
    }
}

// ---------------------------------------------------------------------------
// attn: fused QK^T recompute + exp-scale + E@V. Q resident; K/V + stats
// cp.async double-buffered; 1 sync per k-tile.
// smem u32 layout: Q @0 (8192); KV buf{0,1} @8192 + buf*8224; stats @24640 + buf*128
// ---------------------------------------------------------------------------
#define AT_U32   (8192 + 2*8224 + 2*128)
#define AT_BYTES (AT_U32*4)

__global__ __launch_bounds__(256) void attn(const float* __restrict__ cm,
                                            const float* __restrict__ cr)
{
    extern __shared__ uint32_t su[];
    const uint32_t sb = smem_u32(su);
    const int tid = threadIdx.x, lane = tid & 31, w = tid >> 5;
    const int g = lane >> 2, t = lane & 3;
    const int bh = blockIdx.x, qt0 = blockIdx.y << 7;
    const int b = bh >> 4, h = bh & 15;

    // stage Q resident
    {
        const int srow = tid >> 1, sh = tid & 1;
        const int sw = (srow >> 1) & 3;
        const int st0 = (srow << 4) + (((2*sh)   ^ sw) << 2);
        const int st1 = (srow << 4) + (((2*sh+1) ^ sw) << 2);
#pragma unroll
        for (int arr = 0; arr < 2; arr++)
#pragma unroll
            for (int dblk = 0; dblk < 2; dblk++){
                const uint32_t* src = (arr ? g_Ql : g_Qh)
                    + (size_t)(b*SSQ + qt0 + srow)*512 + h*32 + dblk*16 + sh*8;
                int base = arr*4096 + dblk*2048;
                *(uint4*)&su[base + st0] = *(const uint4*)src;
                *(uint4*)&su[base + st1] = *(const uint4*)(src + 4);
            }
    }

    const int krow = tid >> 2, kdb = (tid >> 1) & 1, khh = tid & 1;
    const int ksw = (krow >> 1) & 3;
    const int kst0 = (krow << 4) + (((2*khh)   ^ ksw) << 2);
    const int kst1 = (krow << 4) + (((2*khh+1) ^ ksw) << 2);

#define KSTAGE(kt, buf) do { \
        size_t go = (size_t)(b*SSQ + (kt)*64 + krow)*512 + h*32 + kdb*16 + khh*8; \
        const uint32_t* srcs[4] = { g_Kh + go, g_Kl + go, g_Vh + go, g_Vl + go }; \
        _Pragma("unroll") \
        for (int arr = 0; arr < 4; arr++){ \
            int base = 8192 + (buf)*8224 + arr*2056 + kdb*1028; \
            cpa16(sb + 4*(base + kst0), srcs[arr]); \
            cpa16(sb + 4*(base + kst1), srcs[arr] + 4); \
        } \
        if (tid < 16) \
            cpa16(sb + 4*(24640 + (buf)*128 + tid*4), cm + (size_t)bh*SSQ + (kt)*64 + tid*4); \
        else if (tid < 32) \
            cpa16(sb + 4*(24640 + (buf)*128 + 64 + (tid-16)*4), cr + (size_t)bh*SSQ + (kt)*64 + (tid-16)*4); \
        CP_COMMIT; } while(0)

    float accO[8][4];
#pragma unroll
    for (int nt = 0; nt < 8; nt++)
#pragma unroll
        for (int j = 0; j < 4; j++) accO[nt][j] = 0.f;

    KSTAGE(0, 0);

    for (int kt = 0; kt < 32; kt++){
        const int buf = kt & 1;
        CP_WAIT0;
        __syncthreads();
        if (kt < 31) KSTAGE(kt + 1, buf ^ 1);

        const int kvb = 8192 + buf*8224;
        const float* mS = (const float*)(su + 24640 + buf*128);
        const float* rS = mS + 64;

        // S = Q K^T  (warp's 16 q rows x 64 keys)
        float accs[8][4];
#pragma unroll
        for (int nt = 0; nt < 8; nt++)
#pragma unroll
            for (int j = 0; j < 4; j++) accs[nt][j] = 0.f;

#pragma unroll
        for (int kcd = 0; kcd < 4; kcd++){
            int dblk = kcd >> 1, kc = kcd & 1;
            uint32_t qh[4], ql[4];
            uint32_t aq = sb + 4*(dblk*2048 + swo(w*16 + (lane & 15), 2*kc + (lane >> 4)));
            ldsm4(qh, aq);
            ldsm4(ql, aq + 4096*4);
            int rK = (lane & 7);
            int cK = 2*kc + ((lane >> 3) & 1);
#pragma unroll
            for (int nt = 0; nt < 8; nt++){
                uint32_t ak = sb + 4*(kvb + dblk*1028 + swo(nt*8 + rK, cK));
                uint32_t k0h, k1h, k0l, k1l;
                ldsm2(k0h, k1h, ak);
                ldsm2(k0l, k1l, ak + 2056*4);
                mma16(accs[nt], qh[0],qh[1],qh[2],qh[3], k0h, k1h);
                mma16(accs[nt], ql[0],ql[1],ql[2],ql[3], k0h, k1h);
                mma16(accs[nt], qh[0],qh[1],qh[2],qh[3], k0l, k1l);
            }
        }

        // E = exp(s - m[k]) * r[k]; in-register repack C-frag -> A-frag
        uint32_t EH[4][4], EL[4][4];
#pragma unroll
        for (int nt = 0; nt < 8; nt++){
            int kcp = nt >> 1, rb = (nt & 1) << 1;
            int c0 = nt*8 + t*2, c1 = c0 + 1;
            float m0 = mS[c0], m1 = mS[c1], r0 = rS[c0], r1 = rS[c1];
            float e00 = __expf(accs[nt][0] - m0) * r0;
            float e01 = __expf(accs[nt][1] - m1) * r1;
            float e10 = __expf(accs[nt][2] - m0) * r0;
            float e11 = __expf(accs[nt][3] - m1) * r1;
            uint32_t hh, ll;
            split2(e00, e01, hh, ll); EH[kcp][rb]   = hh; EL[kcp][rb]   = ll;
            split2(e10, e11, hh, ll); EH[kcp][rb+1] = hh; EL[kcp][rb+1] = ll;
        }

        // O += E @ V  (V frags via ldmatrix.trans; pairs along key)
#pragma unroll
        for (int ntd = 0; ntd < 8; ntd++){
            int dbd = ntd >> 2, ch = ntd & 3;
#pragma unroll
            for (int kcp = 0; kcp < 2; kcp++){
                uint32_t vh4[4], vl4[4];
                uint32_t av = sb + 4*(kvb + 2*2056 + dbd*1028 + swo(kcp*32 + lane, ch));
                ldsm4t(vh4, av);
                ldsm4t(vl4, av + 2056*4);
                int ka = 2*kcp, kb = 2*kcp + 1;
                mma16(accO[ntd], EH[ka][0],EH[ka][1],EH[ka][2],EH[ka][3], vh4[0], vh4[1]);
                mma16(accO[ntd], EL[ka][0],EL[ka][1],EL[ka][2],EL[ka][3], vh4[0], vh4[1]);
                mma16(accO[ntd], EH[ka][0],EH[ka][1],EH[ka][2],EH[ka][3], vl4[0], vl4[1]);
                mma16(accO[ntd], EH[kb][0],EH[kb][1],EH[kb][2],EH[kb][3], vh4[2], vh4[3]);
                mma16(accO[ntd], EL[kb][0],EL[kb][1],EL[kb][2],EL[kb][3], vh4[2], vh4[3]);
                mma16(accO[ntd], EH[kb][0],EH[kb][1],EH[kb][2],EH[kb][3], vl4[2], vl4[3]);
            }
        }
    }
#undef KSTAGE

    // write split Ao
    const int row = qt0 + w*16 + g;
#pragma unroll
    for (int nt = 0; nt < 8; nt++){
        int col = nt*8 + t*2;
        uint32_t hh, ll;
        split2(accO[nt][0], accO[nt][1], hh, ll);
        g_Aoh[(size_t)(b*SSQ + row)*512 + h*32 + (col>>1)] = hh;
        g_Aol[(size_t)(b*SSQ + row)*512 + h*32 + (col>>1)] = ll;
        split2(accO[nt][2], accO[nt][3], hh, ll);
        g_Aoh[(size_t)(b*SSQ + row + 8)*512 + h*32 + (col>>1)] = hh;
        g_Aol[(size_t)(b*SSQ + row + 8)*512 + h*32 + (col>>1)] = ll;
    }
}

// ---------------------------------------------------------------------------
// Launch
// ---------------------------------------------------------------------------
extern "C" void kernel_launch(void* const* d_in, const int* in_sizes, int n_in,
                              void* d_out, int out_size)
{
    const float* qin = (const float*)d_in[0];
    const float* kin = (const float*)d_in[1];
    const float* vin = (const float*)d_in[2];
    const float* Wq  = (const float*)d_in[3];
    const float* bq  = (const float*)d_in[4];
    const float* Wk  = (const float*)d_in[5];
    const float* bk  = (const float*)d_in[6];
    const float* Wv  = (const float*)d_in[7];
    const float* bv  = (const float*)d_in[8];
    const float* Wo  = (const float*)d_in[9];
    const float* bo  = (const float*)d_in[10];

    uint32_t *wth, *wtl, *xh, *xl, *Qh, *Ql, *Kh, *Kl, *Vh, *Vl, *Aoh, *Aol;
    float *cm, *cr;
    cudaGetSymbolAddress((void**)&wth, g_wth);
    cudaGetSymbolAddress((void**)&wtl, g_wtl);
    cudaGetSymbolAddress((void**)&xh,  g_xh);
    cudaGetSymbolAddress((void**)&xl,  g_xl);
    cudaGetSymbolAddress((void**)&Qh,  g_Qh);
    cudaGetSymbolAddress((void**)&Ql,  g_Ql);
    cudaGetSymbolAddress((void**)&Kh,  g_Kh);
    cudaGetSymbolAddress((void**)&Kl,  g_Kl);
    cudaGetSymbolAddress((void**)&Vh,  g_Vh);
    cudaGetSymbolAddress((void**)&Vl,  g_Vl);
    cudaGetSymbolAddress((void**)&Aoh, g_Aoh);
    cudaGetSymbolAddress((void**)&Aol, g_Aol);
    cudaGetSymbolAddress((void**)&cm,  g_cm);
    cudaGetSymbolAddress((void**)&cr,  g_cr);

    cudaFuncSetAttribute(attn, cudaFuncAttributeMaxDynamicSharedMemorySize, AT_BYTES);

    const size_t XS = (size_t)MR*512;
    const size_t WS = (size_t)DM*512;

    inprep<<<MR*512/256, 256>>>(qin, xh + 0*XS, xl + 0*XS);
    inprep<<<MR*512/256, 256>>>(kin, xh + 1*XS, xl + 1*XS);
    inprep<<<MR*512/256, 256>>>(vin, xh + 2*XS, xl + 2*XS);

    dim3 gW(16, 32);
    wprep<<<gW, 256>>>(Wq, wth + 0*WS, wtl + 0*WS);
    wprep<<<gW, 256>>>(Wk, wth + 1*WS, wtl + 1*WS);
    wprep<<<gW, 256>>>(Wv, wth + 2*WS, wtl + 2*WS);
    wprep<<<gW, 256>>>(Wo, wth + 3*WS, wtl + 3*WS);

    dim3 gP(DM/128, MR/128);   // (8, 64)
    proj_ms<<<gP, 256>>>(xh + 0*XS, xl + 0*XS, wth + 0*WS, wtl + 0*WS, bq, Qh, Ql, nullptr);
    proj_ms<<<gP, 256>>>(xh + 1*XS, xl + 1*XS, wth + 1*WS, wtl + 1*WS, bk, Kh, Kl, nullptr);
    proj_ms<<<gP, 256>>>(xh + 2*XS, xl + 2*XS, wth + 2*WS, wtl + 2*WS, bv, Vh, Vl, nullptr);

    colstats<<<dim3(BB*NH, SSQ/128), 256>>>(cm, cr);

    attn<<<dim3(BB*NH, SSQ/128), 256, AT_BYTES>>>(cm, cr);

    proj_ms<<<gP, 256>>>(Aoh, Aol, wth + 3*WS, wtl + 3*WS, bo, nullptr, nullptr, (float*)d_out);
}

// round 8
// speedup vs baseline: 1.6719x; 1.0279x over previous
#include <cuda_runtime.h>
#include <cuda_bf16.h>
#include <stdint.h>

#define BB 4
#define SSQ 2048
#define DM 1024
#define NH 16
#define MR (BB*SSQ)

// ---------------------------------------------------------------------------
// Scratch: u32 = 2 bf16 (pair along contraction dim)
// ---------------------------------------------------------------------------
__device__ uint32_t g_wth[4*DM*512], g_wtl[4*DM*512];       // W^T split [n][kpair]
__device__ uint32_t g_xh[3u*MR*512], g_xl[3u*MR*512];       // split inputs
__device__ uint32_t g_Qh[MR*512], g_Ql[MR*512];
__device__ uint32_t g_Kh[MR*512], g_Kl[MR*512];
__device__ uint32_t g_Vh[MR*512], g_Vl[MR*512];
__device__ uint32_t g_Aoh[MR*512], g_Aol[MR*512];
__device__ float g_cm[BB*NH*SSQ], g_cr[BB*NH*SSQ];

// ---------------------------------------------------------------------------
// helpers
// ---------------------------------------------------------------------------
__device__ __forceinline__ void split2(float x, float y, uint32_t& hi, uint32_t& lo){
    __nv_bfloat16 hx = __float2bfloat16(x);
    __nv_bfloat16 hy = __float2bfloat16(y);
    float rx = x - __bfloat162float(hx);
    float ry = y - __bfloat162float(hy);
    __nv_bfloat162 h2 = __halves2bfloat162(hx, hy);
    __nv_bfloat162 l2 = __halves2bfloat162(__float2bfloat16(rx), __float2bfloat16(ry));
    hi = *reinterpret_cast<uint32_t*>(&h2);
    lo = *reinterpret_cast<uint32_t*>(&l2);
}

__device__ __forceinline__ void mma16(float* d,
    uint32_t a0, uint32_t a1, uint32_t a2, uint32_t a3, uint32_t b0, uint32_t b1)
{
    asm volatile(
        "mma.sync.aligned.m16n8k16.row.col.f32.bf16.bf16.f32 "
        "{%0,%1,%2,%3}, {%4,%5,%6,%7}, {%8,%9}, {%0,%1,%2,%3};\n"
        : "+f"(d[0]), "+f"(d[1]), "+f"(d[2]), "+f"(d[3])
        : "r"(a0), "r"(a1), "r"(a2), "r"(a3), "r"(b0), "r"(b1));
}

__device__ __forceinline__ uint32_t smem_u32(const void* p){
    uint32_t a;
    asm("{ .reg .u64 t; cvta.to.shared.u64 t, %1; cvt.u32.u64 %0, t; }" : "=r"(a) : "l"(p));
    return a;
}

__device__ __forceinline__ void ldsm4(uint32_t* r, uint32_t addr){
    asm volatile("ldmatrix.sync.aligned.m8n8.x4.shared.b16 {%0,%1,%2,%3}, [%4];"
        : "=r"(r[0]), "=r"(r[1]), "=r"(r[2]), "=r"(r[3]) : "r"(addr));
}
__device__ __forceinline__ void ldsm4t(uint32_t* r, uint32_t addr){
    asm volatile("ldmatrix.sync.aligned.m8n8.x4.trans.shared.b16 {%0,%1,%2,%3}, [%4];"
        : "=r"(r[0]), "=r"(r[1]), "=r"(r[2]), "=r"(r[3]) : "r"(addr));
}

__device__ __forceinline__ void cpa16(uint32_t dst, const void* src){
    asm volatile("cp.async.cg.shared.global [%0], [%1], 16;\n" :: "r"(dst), "l"(src));
}
#define CP_COMMIT asm volatile("cp.async.commit_group;\n" ::: "memory")
#define CP_WAIT0  asm volatile("cp.async.wait_group 0;\n" ::: "memory")

// swizzled u32 offset inside a [rows][16 u32] tile: chunk c (0..3) of 4 u32
__device__ __forceinline__ int swo(int r, int c){
    return (r << 4) + (((c ^ ((r >> 1) & 3))) << 2);
}

// ---------------------------------------------------------------------------
// prepass: split f32 -> bf16 hi/lo pairs (merged over q/k/v via grid.y)
// ---------------------------------------------------------------------------
__global__ __launch_bounds__(256) void inprep3(const float* __restrict__ q,
    const float* __restrict__ k, const float* __restrict__ v)
{
    const int y = blockIdx.y;
    const float* in = (y == 0) ? q : (y == 1) ? k : v;
    size_t i = (size_t)blockIdx.x*256 + threadIdx.x;
    float2 vv = *(const float2*)(in + 2*i);
    uint32_t hh, ll; split2(vv.x, vv.y, hh, ll);
    g_xh[(size_t)y*MR*512 + i] = hh;
    g_xl[(size_t)y*MR*512 + i] = ll;
}

// W [k][n] f32 -> Wt split [n][512] u32 pairs along k
__global__ __launch_bounds__(256) void wprep(const float* __restrict__ W,
    uint32_t* __restrict__ oh, uint32_t* __restrict__ ol)
{
    __shared__ float t[64][33];
    const int k0 = blockIdx.x << 6, n0 = blockIdx.y << 5;
    const int tid = threadIdx.x;
#pragma unroll
    for (int i = 0; i < 8; i++){
        int v = i*256 + tid;
        int r = v >> 5, c = v & 31;
        t[r][c] = W[(size_t)(k0 + r)*DM + n0 + c];
    }
    __syncthreads();
    const int n = tid >> 3, pi = (tid & 7) << 2;
    uint4 H, L; uint32_t h, l;
    split2(t[2*pi][n],   t[2*pi+1][n], h, l); H.x = h; L.x = l;
    split2(t[2*pi+2][n], t[2*pi+3][n], h, l); H.y = h; L.y = l;
    split2(t[2*pi+4][n], t[2*pi+5][n], h, l); H.z = h; L.z = l;
    split2(t[2*pi+6][n], t[2*pi+7][n], h, l); H.w = h; L.w = l;
    size_t o = (size_t)(n0 + n)*512 + (k0 >> 1) + pi;
    *(uint4*)(oh + o) = H;
    *(uint4*)(ol + o) = L;
}

// ---------------------------------------------------------------------------
// proj body: C = A @ W + bias. 3-pass split mma, cp.async double-buffered.
// CTA 128x128, BK=32, 256 thr (8 warps 2x4, warp 64x32).
// ---------------------------------------------------------------------------
__device__ __forceinline__ void proj_body(
    const uint32_t* __restrict__ Ah, const uint32_t* __restrict__ Al,
    const uint32_t* __restrict__ Bh, const uint32_t* __restrict__ Bl,
    const float* __restrict__ bias,
    uint32_t* __restrict__ oh, uint32_t* __restrict__ ol,
    float* __restrict__ of, uint32_t* S)
{
    const int tid = threadIdx.x, lane = tid & 31, w = tid >> 5;
    const int wy = w >> 2, wx = w & 3;
    const int brow = blockIdx.y << 7, bcol = blockIdx.x << 7;
    const uint32_t sb = smem_u32(S);

    const int srow = tid >> 1, sh = tid & 1;
    const int sw = (srow >> 1) & 3;
    const int st0 = (srow << 4) + (((2*sh)   ^ sw) << 2);
    const int st1 = (srow << 4) + (((2*sh+1) ^ sw) << 2);

    const uint32_t* gA0 = Ah + (size_t)(brow + srow)*512 + sh*8;
    const uint32_t* gA1 = Al + (size_t)(brow + srow)*512 + sh*8;
    const uint32_t* gB0 = Bh + (size_t)(bcol + srow)*512 + sh*8;
    const uint32_t* gB1 = Bl + (size_t)(bcol + srow)*512 + sh*8;

#define PSTAGE(s, B) do { \
        int o = (s) << 4; \
        cpa16(sb + 4*((B) + st0),        gA0 + o); cpa16(sb + 4*((B) + st1),        gA0 + o + 4); \
        cpa16(sb + 4*((B) + 2048 + st0), gA1 + o); cpa16(sb + 4*((B) + 2048 + st1), gA1 + o + 4); \
        cpa16(sb + 4*((B) + 4096 + st0), gB0 + o); cpa16(sb + 4*((B) + 4096 + st1), gB0 + o + 4); \
        cpa16(sb + 4*((B) + 6144 + st0), gB1 + o); cpa16(sb + 4*((B) + 6144 + st1), gB1 + o + 4); \
        CP_COMMIT; } while(0)

    float acc[4][4][4];
#pragma unroll
    for (int mt = 0; mt < 4; mt++)
#pragma unroll
        for (int nt = 0; nt < 4; nt++)
#pragma unroll
            for (int j = 0; j < 4; j++) acc[mt][nt][j] = 0.f;

    PSTAGE(0, 0);

    for (int it = 0; it < 32; it++){
        const int B = (it & 1) << 13;
        CP_WAIT0;
        __syncthreads();
        if (it < 31) PSTAGE(it + 1, ((it + 1) & 1) << 13);

        uint32_t bhv[4][4], blv[4][4];
#pragma unroll
        for (int nt = 0; nt < 4; nt++){
            int rB = wx*32 + nt*8 + (lane & 7);
            int cB = lane >> 3;
            uint32_t ad = sb + 4*(B + 4096 + swo(rB, cB));
            ldsm4(bhv[nt], ad);
            ldsm4(blv[nt], ad + 2048*4);
        }
#pragma unroll
        for (int kc = 0; kc < 2; kc++){
#pragma unroll
            for (int mt = 0; mt < 4; mt++){
                uint32_t ahv[4], alv[4];
                int rA = wy*64 + mt*16 + (lane & 15);
                int cA = 2*kc + (lane >> 4);
                uint32_t ad = sb + 4*(B + swo(rA, cA));
                ldsm4(ahv, ad);
                ldsm4(alv, ad + 2048*4);
#pragma unroll
                for (int nt = 0; nt < 4; nt++){
                    mma16(acc[mt][nt], ahv[0],ahv[1],ahv[2],ahv[3], bhv[nt][2*kc], bhv[nt][2*kc+1]);
                    mma16(acc[mt][nt], alv[0],alv[1],alv[2],alv[3], bhv[nt][2*kc], bhv[nt][2*kc+1]);
                    mma16(acc[mt][nt], ahv[0],ahv[1],ahv[2],ahv[3], blv[nt][2*kc], blv[nt][2*kc+1]);
                }
            }
        }
    }
#undef PSTAGE

#pragma unroll
    for (int mt = 0; mt < 4; mt++)
#pragma unroll
        for (int nt = 0; nt < 4; nt++){
            int row = brow + wy*64 + mt*16 + (lane >> 2);
            int col = bcol + wx*32 + nt*8 + ((lane & 3) << 1);
            float b0 = bias[col], b1 = bias[col+1];
            float v0 = acc[mt][nt][0] + b0, v1 = acc[mt][nt][1] + b1;
            float v2 = acc[mt][nt][2] + b0, v3 = acc[mt][nt][3] + b1;
            if (of){
                *(float2*)(of + (size_t)row*DM + col)     = make_float2(v0, v1);
                *(float2*)(of + (size_t)(row+8)*DM + col) = make_float2(v2, v3);
            } else {
                uint32_t hh, ll;
                split2(v0, v1, hh, ll);
                oh[(size_t)row*512 + (col>>1)] = hh; ol[(size_t)row*512 + (col>>1)] = ll;
                split2(v2, v3, hh, ll);
                oh[(size_t)(row+8)*512 + (col>>1)] = hh; ol[(size_t)(row+8)*512 + (col>>1)] = ll;
            }
        }
}

// merged Q/K/V projection: blockIdx.z selects stream
__global__ __launch_bounds__(256) void proj_qkv(
    const float* __restrict__ bq, const float* __restrict__ bk,
    const float* __restrict__ bv)
{
    __shared__ uint32_t S[16384];
    const int z = blockIdx.z;
    const uint32_t* Ah = g_xh + (size_t)z*MR*512;
    const uint32_t* Al = g_xl + (size_t)z*MR*512;
    const uint32_t* Bh = g_wth + (size_t)z*DM*512;
    const uint32_t* Bl = g_wtl + (size_t)z*DM*512;
    const float* bias = (z == 0) ? bq : (z == 1) ? bk : bv;
    uint32_t* oh = (z == 0) ? g_Qh : (z == 1) ? g_Kh : g_Vh;
    uint32_t* ol = (z == 0) ? g_Ql : (z == 1) ? g_Kl : g_Vl;
    proj_body(Ah, Al, Bh, Bl, bias, oh, ol, nullptr, S);
}

// output projection (f32 out)
__global__ __launch_bounds__(256) void proj_wo(const float* __restrict__ bo,
                                               float* __restrict__ out)
{
    __shared__ uint32_t S[16384];
    proj_body(g_Aoh, g_Aol, g_wth + (size_t)3*DM*512, g_wtl + (size_t)3*DM*512,
              bo, nullptr, nullptr, out, S);
}

// ---------------------------------------------------------------------------
// colstats: per-key-column max/sumexp over all queries (softmax over q axis).
// K frags direct from global; Q via cp.async double-buffered smem tiles.
// ---------------------------------------------------------------------------
__global__ __launch_bounds__(256) void colstats(float* __restrict__ cm,
                                                float* __restrict__ cr)
{
    __shared__ uint32_t S[16384];
    const int tid = threadIdx.x, lane = tid & 31, w = tid >> 5;
    const int bh = blockIdx.x, kt0 = blockIdx.y << 7;
    const int b = bh >> 4, h = bh & 15;
    const uint32_t sb = smem_u32(S);

    uint2 kbh[2][4], kbl[2][4];
#pragma unroll
    for (int nt2 = 0; nt2 < 2; nt2++)
#pragma unroll
        for (int kc = 0; kc < 4; kc++){
            int key = kt0 + w*16 + nt2*8 + (lane >> 2);
            size_t o = (size_t)(b*SSQ + key)*512 + h*32 + kc*8 + (lane & 3);
            kbh[nt2][kc] = make_uint2(g_Kh[o], g_Kh[o+4]);
            kbl[nt2][kc] = make_uint2(g_Kl[o], g_Kl[o+4]);
        }

    const int srow = tid >> 1, sh = tid & 1;
    const int sw = (srow >> 1) & 3;
    const int st0 = (srow << 4) + (((2*sh)   ^ sw) << 2);
    const int st1 = (srow << 4) + (((2*sh+1) ^ sw) << 2);

#define QSTAGE(qt, B) do { \
        _Pragma("unroll") \
        for (int arr = 0; arr < 2; arr++){ \
            _Pragma("unroll") \
            for (int dblk = 0; dblk < 2; dblk++){ \
                const uint32_t* src = (arr ? g_Ql : g_Qh) \
                    + (size_t)(b*SSQ + (qt)*128 + srow)*512 + h*32 + dblk*16 + sh*8; \
                int base = (B) + arr*4096 + dblk*2048; \
                cpa16(sb + 4*(base + st0), src); \
                cpa16(sb + 4*(base + st1), src + 4); \
            } \
        } \
        CP_COMMIT; } while(0)

    float mst[4] = {-1e30f, -1e30f, -1e30f, -1e30f};
    float zst[4] = {0.f, 0.f, 0.f, 0.f};

    QSTAGE(0, 0);

    for (int qt = 0; qt < 16; qt++){
        const int B = (qt & 1) << 13;
        CP_WAIT0;
        __syncthreads();
        if (qt < 15) QSTAGE(qt + 1, ((qt + 1) & 1) << 13);

        float acc[8][2][4];
#pragma unroll
        for (int mt = 0; mt < 8; mt++)
#pragma unroll
            for (int nt2 = 0; nt2 < 2; nt2++)
#pragma unroll
                for (int j = 0; j < 4; j++) acc[mt][nt2][j] = 0.f;

#pragma unroll
        for (int mt = 0; mt < 8; mt++)
#pragma unroll
            for (int kcd = 0; kcd < 4; kcd++){
                int dblk = kcd >> 1, kc = kcd & 1;
                uint32_t qh[4], ql[4];
                int rA = mt*16 + (lane & 15);
                int cA = 2*kc + (lane >> 4);
                uint32_t ad = sb + 4*(B + dblk*2048 + swo(rA, cA));
                ldsm4(qh, ad);
                ldsm4(ql, ad + 4096*4);
#pragma unroll
                for (int nt2 = 0; nt2 < 2; nt2++){
                    mma16(acc[mt][nt2], qh[0],qh[1],qh[2],qh[3], kbh[nt2][kcd].x, kbh[nt2][kcd].y);
                    mma16(acc[mt][nt2], ql[0],ql[1],ql[2],ql[3], kbh[nt2][kcd].x, kbh[nt2][kcd].y);
                    mma16(acc[mt][nt2], qh[0],qh[1],qh[2],qh[3], kbl[nt2][kcd].x, kbl[nt2][kcd].y);
                }
            }

#pragma unroll
        for (int nt2 = 0; nt2 < 2; nt2++)
#pragma unroll
            for (int hh = 0; hh < 2; hh++){
                int si = nt2*2 + hh;
                float tmax = -1e30f;
#pragma unroll
                for (int mt = 0; mt < 8; mt++)
                    tmax = fmaxf(tmax, fmaxf(acc[mt][nt2][hh], acc[mt][nt2][hh+2]));
                tmax = fmaxf(tmax, __shfl_xor_sync(0xffffffffu, tmax, 4));
                tmax = fmaxf(tmax, __shfl_xor_sync(0xffffffffu, tmax, 8));
                tmax = fmaxf(tmax, __shfl_xor_sync(0xffffffffu, tmax, 16));
                float mn = fmaxf(mst[si], tmax);
                float ts = 0.f;
#pragma unroll
                for (int mt = 0; mt < 8; mt++)
                    ts += __expf(acc[mt][nt2][hh] - mn) + __expf(acc[mt][nt2][hh+2] - mn);
                ts += __shfl_xor_sync(0xffffffffu, ts, 4);
                ts += __shfl_xor_sync(0xffffffffu, ts, 8);
                ts += __shfl_xor_sync(0xffffffffu, ts, 16);
                zst[si] = zst[si] * __expf(mst[si] - mn) + ts;
                mst[si] = mn;
            }
    }
#undef QSTAGE

    if (lane < 4){
#pragma unroll
        for (int nt2 = 0; nt2 < 2; nt2++)
#pragma unroll
            for (int hh = 0; hh < 2; hh++){
                int col = kt0 + w*16 + nt2*8 + lane*2 + hh;
                cm[(size_t)bh*SSQ + col] = mst[nt2*2 + hh];
                cr[(size_t)bh*SSQ + col] = 1.0f / (8.0f * zst[nt2*2 + hh]);
            }
    }
}

// ---------------------------------------------------------------------------
// attn: fused QK^T recompute + exp-scale + E@V. Q resident; K/V + stats
// cp.async double-buffered; 1 sync per k-tile. K frags via ldsm4 (2 blocks).
// ---------------------------------------------------------------------------
#define AT_U32   (8192 + 2*8224 + 2*128)
#define AT_BYTES (AT_U32*4)

__global__ __launch_bounds__(256) void attn(const float* __restrict__ cm,
                                            const float* __restrict__ cr)
{
    extern __shared__ uint32_t su[];
    const uint32_t sb = smem_u32(su);
    const int tid = threadIdx.x, lane = tid & 31, w = tid >> 5;
    const int g = lane >> 2, t = lane & 3;
    const int bh = blockIdx.x, qt0 = blockIdx.y << 7;
    const int b = bh >> 4, h = bh & 15;

    // stage Q resident
    {
        const int srow = tid >> 1, sh = tid & 1;
        const int sw = (srow >> 1) & 3;
        const int st0 = (srow << 4) + (((2*sh)   ^ sw) << 2);
        const int st1 = (srow << 4) + (((2*sh+1) ^ sw) << 2);
#pragma unroll
        for (int arr = 0; arr < 2; arr++)
#pragma unroll
            for (int dblk = 0; dblk < 2; dblk++){
                const uint32_t* src = (arr ? g_Ql : g_Qh)
                    + (size_t)(b*SSQ + qt0 + srow)*512 + h*32 + dblk*16 + sh*8;
                int base = arr*4096 + dblk*2048;
                *(uint4*)&su[base + st0] = *(const uint4*)src;
                *(uint4*)&su[base + st1] = *(const uint4*)(src + 4);
            }
    }

    const int krow = tid >> 2, kdb = (tid >> 1) & 1, khh = tid & 1;
    const int ksw = (krow >> 1) & 3;
    const int kst0 = (krow << 4) + (((2*khh)   ^ ksw) << 2);
    const int kst1 = (krow << 4) + (((2*khh+1) ^ ksw) << 2);

#define KSTAGE(kt, buf) do { \
        size_t go = (size_t)(b*SSQ + (kt)*64 + krow)*512 + h*32 + kdb*16 + khh*8; \
        const uint32_t* srcs[4] = { g_Kh + go, g_Kl + go, g_Vh + go, g_Vl + go }; \
        _Pragma("unroll") \
        for (int arr = 0; arr < 4; arr++){ \
            int base = 8192 + (buf)*8224 + arr*2056 + kdb*1028; \
            cpa16(sb + 4*(base + kst0), srcs[arr]); \
            cpa16(sb + 4*(base + kst1), srcs[arr] + 4); \
        } \
        if (tid < 16) \
            cpa16(sb + 4*(24640 + (buf)*128 + tid*4), cm + (size_t)bh*SSQ + (kt)*64 + tid*4); \
        else if (tid < 32) \
            cpa16(sb + 4*(24640 + (buf)*128 + 64 + (tid-16)*4), cr + (size_t)bh*SSQ + (kt)*64 + (tid-16)*4); \
        CP_COMMIT; } while(0)

    float accO[8][4];
#pragma unroll
    for (int nt = 0; nt < 8; nt++)
#pragma unroll
        for (int j = 0; j < 4; j++) accO[nt][j] = 0.f;

    KSTAGE(0, 0);

    for (int kt = 0; kt < 32; kt++){
        const int buf = kt & 1;
        CP_WAIT0;
        __syncthreads();
        if (kt < 31) KSTAGE(kt + 1, buf ^ 1);

        const int kvb = 8192 + buf*8224;
        const float* mS = (const float*)(su + 24640 + buf*128);
        const float* rS = mS + 64;

        // S = Q K^T  (warp's 16 q rows x 64 keys); K frags by ldsm4 pairs
        float accs[8][4];
#pragma unroll
        for (int nt = 0; nt < 8; nt++)
#pragma unroll
            for (int j = 0; j < 4; j++) accs[nt][j] = 0.f;

#pragma unroll
        for (int kcd = 0; kcd < 4; kcd++){
            int dblk = kcd >> 1, kc = kcd & 1;
            uint32_t qh[4], ql[4];
            uint32_t aq = sb + 4*(dblk*2048 + swo(w*16 + (lane & 15), 2*kc + (lane >> 4)));
            ldsm4(qh, aq);
            ldsm4(ql, aq + 4096*4);
            // K fragment addresses: lanes 0-15 -> even nt block, 16-31 -> odd
            int rK = lane & 7;
            int cK = 2*kc + ((lane >> 3) & 1);
            int ntSel = lane >> 4;           // 0 or 1
#pragma unroll
            for (int ntp = 0; ntp < 4; ntp++){
                int ntX = 2*ntp + ntSel;
                uint32_t ak = sb + 4*(kvb + dblk*1028 + swo(ntX*8 + rK, cK));
                uint32_t kfh[4], kfl[4];
                ldsm4(kfh, ak);
                ldsm4(kfl, ak + 2056*4);
                mma16(accs[2*ntp],   qh[0],qh[1],qh[2],qh[3], kfh[0], kfh[1]);
                mma16(accs[2*ntp],   ql[0],ql[1],ql[2],ql[3], kfh[0], kfh[1]);
                mma16(accs[2*ntp],   qh[0],qh[1],qh[2],qh[3], kfl[0], kfl[1]);
                mma16(accs[2*ntp+1], qh[0],qh[1],qh[2],qh[3], kfh[2], kfh[3]);
                mma16(accs[2*ntp+1], ql[0],ql[1],ql[2],ql[3], kfh[2], kfh[3]);
                mma16(accs[2*ntp+1], qh[0],qh[1],qh[2],qh[3], kfl[2], kfl[3]);
            }
        }

        // E = exp(s - m[k]) * r[k]; in-register repack C-frag -> A-frag
        uint32_t EH[4][4], EL[4][4];
#pragma unroll
        for (int nt = 0; nt < 8; nt++){
            int kcp = nt >> 1, rb = (nt & 1) << 1;
            int c0 = nt*8 + t*2, c1 = c0 + 1;
            float m0 = mS[c0], m1 = mS[c1], r0 = rS[c0], r1 = rS[c1];
            float e00 = __expf(accs[nt][0] - m0) * r0;
            float e01 = __expf(accs[nt][1] - m1) * r1;
            float e10 = __expf(accs[nt][2] - m0) * r0;
            float e11 = __expf(accs[nt][3] - m1) * r1;
            uint32_t hh, ll;
            split2(e00, e01, hh, ll); EH[kcp][rb]   = hh; EL[kcp][rb]   = ll;
            split2(e10, e11, hh, ll); EH[kcp][rb+1] = hh; EL[kcp][rb+1] = ll;
        }

        // O += E @ V  (V frags via ldmatrix.trans; pairs along key)
#pragma unroll
        for (int ntd = 0; ntd < 8; ntd++){
            int dbd = ntd >> 2, ch = ntd & 3;
#pragma unroll
            for (int kcp = 0; kcp < 2; kcp++){
                uint32_t vh4[4], vl4[4];
                uint32_t av = sb + 4*(kvb + 2*2056 + dbd*1028 + swo(kcp*32 + lane, ch));
                ldsm4t(vh4, av);
                ldsm4t(vl4, av + 2056*4);
                int ka = 2*kcp, kb = 2*kcp + 1;
                mma16(accO[ntd], EH[ka][0],EH[ka][1],EH[ka][2],EH[ka][3], vh4[0], vh4[1]);
                mma16(accO[ntd], EL[ka][0],EL[ka][1],EL[ka][2],EL[ka][3], vh4[0], vh4[1]);
                mma16(accO[ntd], EH[ka][0],EH[ka][1],EH[ka][2],EH[ka][3], vl4[0], vl4[1]);
                mma16(accO[ntd], EH[kb][0],EH[kb][1],EH[kb][2],EH[kb][3], vh4[2], vh4[3]);
                mma16(accO[ntd], EL[kb][0],EL[kb][1],EL[kb][2],EL[kb][3], vh4[2], vh4[3]);
                mma16(accO[ntd], EH[kb][0],EH[kb][1],EH[kb][2],EH[kb][3], vl4[2], vl4[3]);
            }
        }
    }
#undef KSTAGE

    // write split Ao
    const int row = qt0 + w*16 + g;
#pragma unroll
    for (int nt = 0; nt < 8; nt++){
        int col = nt*8 + t*2;
        uint32_t hh, ll;
        split2(accO[nt][0], accO[nt][1], hh, ll);
        g_Aoh[(size_t)(b*SSQ + row)*512 + h*32 + (col>>1)] = hh;
        g_Aol[(size_t)(b*SSQ + row)*512 + h*32 + (col>>1)] = ll;
        split2(accO[nt][2], accO[nt][3], hh, ll);
        g_Aoh[(size_t)(b*SSQ + row + 8)*512 + h*32 + (col>>1)] = hh;
        g_Aol[(size_t)(b*SSQ + row + 8)*512 + h*32 + (col>>1)] = ll;
    }
}

// ---------------------------------------------------------------------------
// Launch
// ---------------------------------------------------------------------------
extern "C" void kernel_launch(void* const* d_in, const int* in_sizes, int n_in,
                              void* d_out, int out_size)
{
    const float* qin = (const float*)d_in[0];
    const float* kin = (const float*)d_in[1];
    const float* vin = (const float*)d_in[2];
    const float* Wq  = (const float*)d_in[3];
    const float* bq  = (const float*)d_in[4];
    const float* Wk  = (const float*)d_in[5];
    const float* bk  = (const float*)d_in[6];
    const float* Wv  = (const float*)d_in[7];
    const float* bv  = (const float*)d_in[8];
    const float* Wo  = (const float*)d_in[9];
    const float* bo  = (const float*)d_in[10];

    uint32_t *wth, *wtl;
    float *cm, *cr;
    cudaGetSymbolAddress((void**)&wth, g_wth);
    cudaGetSymbolAddress((void**)&wtl, g_wtl);
    cudaGetSymbolAddress((void**)&cm,  g_cm);
    cudaGetSymbolAddress((void**)&cr,  g_cr);

    cudaFuncSetAttribute(attn, cudaFuncAttributeMaxDynamicSharedMemorySize, AT_BYTES);

    const size_t WS = (size_t)DM*512;

    inprep3<<<dim3(MR*512/256, 3), 256>>>(qin, kin, vin);

    dim3 gW(16, 32);
    wprep<<<gW, 256>>>(Wq, wth + 0*WS, wtl + 0*WS);
    wprep<<<gW, 256>>>(Wk, wth + 1*WS, wtl + 1*WS);
    wprep<<<gW, 256>>>(Wv, wth + 2*WS, wtl + 2*WS);
    wprep<<<gW, 256>>>(Wo, wth + 3*WS, wtl + 3*WS);

    proj_qkv<<<dim3(DM/128, MR/128, 3), 256>>>(bq, bk, bv);

    colstats<<<dim3(BB*NH, SSQ/128), 256>>>(cm, cr);

    attn<<<dim3(BB*NH, SSQ/128), 256, AT_BYTES>>>(cm, cr);

    proj_wo<<<dim3(DM/128, MR/128), 256>>>(bo, (float*)d_out);
}

// round 9
// speedup vs baseline: 1.8321x; 1.0959x over previous
#include <cuda_runtime.h>
#include <cuda_bf16.h>
#include <stdint.h>

#define BB 4
#define SSQ 2048
#define DM 1024
#define NH 16
#define MR (BB*SSQ)

// ---------------------------------------------------------------------------
// Scratch: u32 = 2 bf16 (pair along contraction dim)
// ---------------------------------------------------------------------------
__device__ uint32_t g_wth[4*DM*512], g_wtl[4*DM*512];       // W^T split [n][kpair]
__device__ uint32_t g_xh[3u*MR*512], g_xl[3u*MR*512];       // split inputs
__device__ uint32_t g_Qh[MR*512], g_Ql[MR*512];
__device__ uint32_t g_Kh[MR*512], g_Kl[MR*512];
__device__ uint32_t g_Vh[MR*512], g_Vl[MR*512];
__device__ uint32_t g_Aoh[MR*512], g_Aol[MR*512];
__device__ float g_cm[BB*NH*SSQ], g_cr[BB*NH*SSQ];

// ---------------------------------------------------------------------------
// helpers
// ---------------------------------------------------------------------------
__device__ __forceinline__ void split2(float x, float y, uint32_t& hi, uint32_t& lo){
    __nv_bfloat16 hx = __float2bfloat16(x);
    __nv_bfloat16 hy = __float2bfloat16(y);
    float rx = x - __bfloat162float(hx);
    float ry = y - __bfloat162float(hy);
    __nv_bfloat162 h2 = __halves2bfloat162(hx, hy);
    __nv_bfloat162 l2 = __halves2bfloat162(__float2bfloat16(rx), __float2bfloat16(ry));
    hi = *reinterpret_cast<uint32_t*>(&h2);
    lo = *reinterpret_cast<uint32_t*>(&l2);
}

__device__ __forceinline__ void mma16(float* d,
    uint32_t a0, uint32_t a1, uint32_t a2, uint32_t a3, uint32_t b0, uint32_t b1)
{
    asm volatile(
        "mma.sync.aligned.m16n8k16.row.col.f32.bf16.bf16.f32 "
        "{%0,%1,%2,%3}, {%4,%5,%6,%7}, {%8,%9}, {%0,%1,%2,%3};\n"
        : "+f"(d[0]), "+f"(d[1]), "+f"(d[2]), "+f"(d[3])
        : "r"(a0), "r"(a1), "r"(a2), "r"(a3), "r"(b0), "r"(b1));
}

__device__ __forceinline__ uint32_t smem_u32(const void* p){
    uint32_t a;
    asm("{ .reg .u64 t; cvta.to.shared.u64 t, %1; cvt.u32.u64 %0, t; }" : "=r"(a) : "l"(p));
    return a;
}

__device__ __forceinline__ void ldsm4(uint32_t* r, uint32_t addr){
    asm volatile("ldmatrix.sync.aligned.m8n8.x4.shared.b16 {%0,%1,%2,%3}, [%4];"
        : "=r"(r[0]), "=r"(r[1]), "=r"(r[2]), "=r"(r[3]) : "r"(addr));
}
__device__ __forceinline__ void ldsm4t(uint32_t* r, uint32_t addr){
    asm volatile("ldmatrix.sync.aligned.m8n8.x4.trans.shared.b16 {%0,%1,%2,%3}, [%4];"
        : "=r"(r[0]), "=r"(r[1]), "=r"(r[2]), "=r"(r[3]) : "r"(addr));
}

__device__ __forceinline__ void cpa16(uint32_t dst, const void* src){
    asm volatile("cp.async.cg.shared.global [%0], [%1], 16;\n" :: "r"(dst), "l"(src));
}
#define CP_COMMIT asm volatile("cp.async.commit_group;\n" ::: "memory")
#define CP_WAIT0  asm volatile("cp.async.wait_group 0;\n" ::: "memory")

// swizzled u32 offset inside a [rows][16 u32] tile: chunk c (0..3) of 4 u32
__device__ __forceinline__ int swo(int r, int c){
    return (r << 4) + (((c ^ ((r >> 1) & 3))) << 2);
}

// ---------------------------------------------------------------------------
// prepass: split f32 -> bf16 hi/lo pairs (merged over q/k/v via grid.y)
// ---------------------------------------------------------------------------
__global__ __launch_bounds__(256) void inprep3(const float* __restrict__ q,
    const float* __restrict__ k, const float* __restrict__ v)
{
    const int y = blockIdx.y;
    const float* in = (y == 0) ? q : (y == 1) ? k : v;
    size_t i = (size_t)blockIdx.x*256 + threadIdx.x;
    float2 vv = *(const float2*)(in + 2*i);
    uint32_t hh, ll; split2(vv.x, vv.y, hh, ll);
    g_xh[(size_t)y*MR*512 + i] = hh;
    g_xl[(size_t)y*MR*512 + i] = ll;
}

// W [k][n] f32 -> Wt split [n][512] u32 pairs along k
__global__ __launch_bounds__(256) void wprep(const float* __restrict__ W,
    uint32_t* __restrict__ oh, uint32_t* __restrict__ ol)
{
    __shared__ float t[64][33];
    const int k0 = blockIdx.x << 6, n0 = blockIdx.y << 5;
    const int tid = threadIdx.x;
#pragma unroll
    for (int i = 0; i < 8; i++){
        int v = i*256 + tid;
        int r = v >> 5, c = v & 31;
        t[r][c] = W[(size_t)(k0 + r)*DM + n0 + c];
    }
    __syncthreads();
    const int n = tid >> 3, pi = (tid & 7) << 2;
    uint4 H, L; uint32_t h, l;
    split2(t[2*pi][n],   t[2*pi+1][n], h, l); H.x = h; L.x = l;
    split2(t[2*pi+2][n], t[2*pi+3][n], h, l); H.y = h; L.y = l;
    split2(t[2*pi+4][n], t[2*pi+5][n], h, l); H.z = h; L.z = l;
    split2(t[2*pi+6][n], t[2*pi+7][n], h, l); H.w = h; L.w = l;
    size_t o = (size_t)(n0 + n)*512 + (k0 >> 1) + pi;
    *(uint4*)(oh + o) = H;
    *(uint4*)(ol + o) = L;
}

// ---------------------------------------------------------------------------
// proj body: C = A @ W + bias. 3-pass split mma, cp.async double-buffered.
// CTA 128x128, BK=32, 256 thr (8 warps 2x4, warp 64x32). 2 CTAs/SM.
// ---------------------------------------------------------------------------
__device__ __forceinline__ void proj_body(
    const uint32_t* __restrict__ Ah, const uint32_t* __restrict__ Al,
    const uint32_t* __restrict__ Bh, const uint32_t* __restrict__ Bl,
    const float* __restrict__ bias,
    uint32_t* __restrict__ oh, uint32_t* __restrict__ ol,
    float* __restrict__ of, uint32_t* S)
{
    const int tid = threadIdx.x, lane = tid & 31, w = tid >> 5;
    const int wy = w >> 2, wx = w & 3;
    const int brow = blockIdx.y << 7, bcol = blockIdx.x << 7;
    const uint32_t sb = smem_u32(S);

    const int srow = tid >> 1, sh = tid & 1;
    const int sw = (srow >> 1) & 3;
    const int st0 = (srow << 4) + (((2*sh)   ^ sw) << 2);
    const int st1 = (srow << 4) + (((2*sh+1) ^ sw) << 2);

    const uint32_t* gA0 = Ah + (size_t)(brow + srow)*512 + sh*8;
    const uint32_t* gA1 = Al + (size_t)(brow + srow)*512 + sh*8;
    const uint32_t* gB0 = Bh + (size_t)(bcol + srow)*512 + sh*8;
    const uint32_t* gB1 = Bl + (size_t)(bcol + srow)*512 + sh*8;

#define PSTAGE(s, B) do { \
        int o = (s) << 4; \
        cpa16(sb + 4*((B) + st0),        gA0 + o); cpa16(sb + 4*((B) + st1),        gA0 + o + 4); \
        cpa16(sb + 4*((B) + 2048 + st0), gA1 + o); cpa16(sb + 4*((B) + 2048 + st1), gA1 + o + 4); \
        cpa16(sb + 4*((B) + 4096 + st0), gB0 + o); cpa16(sb + 4*((B) + 4096 + st1), gB0 + o + 4); \
        cpa16(sb + 4*((B) + 6144 + st0), gB1 + o); cpa16(sb + 4*((B) + 6144 + st1), gB1 + o + 4); \
        CP_COMMIT; } while(0)

    float acc[4][4][4];
#pragma unroll
    for (int mt = 0; mt < 4; mt++)
#pragma unroll
        for (int nt = 0; nt < 4; nt++)
#pragma unroll
            for (int j = 0; j < 4; j++) acc[mt][nt][j] = 0.f;

    PSTAGE(0, 0);

    for (int it = 0; it < 32; it++){
        const int B = (it & 1) << 13;
        CP_WAIT0;
        __syncthreads();
        if (it < 31) PSTAGE(it + 1, ((it + 1) & 1) << 13);

        uint32_t bhv[4][4], blv[4][4];
#pragma unroll
        for (int nt = 0; nt < 4; nt++){
            int rB = wx*32 + nt*8 + (lane & 7);
            int cB = lane >> 3;
            uint32_t ad = sb + 4*(B + 4096 + swo(rB, cB));
            ldsm4(bhv[nt], ad);
            ldsm4(blv[nt], ad + 2048*4);
        }
#pragma unroll
        for (int kc = 0; kc < 2; kc++){
#pragma unroll
            for (int mt = 0; mt < 4; mt++){
                uint32_t ahv[4], alv[4];
                int rA = wy*64 + mt*16 + (lane & 15);
                int cA = 2*kc + (lane >> 4);
                uint32_t ad = sb + 4*(B + swo(rA, cA));
                ldsm4(ahv, ad);
                ldsm4(alv, ad + 2048*4);
#pragma unroll
                for (int nt = 0; nt < 4; nt++){
                    mma16(acc[mt][nt], ahv[0],ahv[1],ahv[2],ahv[3], bhv[nt][2*kc], bhv[nt][2*kc+1]);
                    mma16(acc[mt][nt], alv[0],alv[1],alv[2],alv[3], bhv[nt][2*kc], bhv[nt][2*kc+1]);
                    mma16(acc[mt][nt], ahv[0],ahv[1],ahv[2],ahv[3], blv[nt][2*kc], blv[nt][2*kc+1]);
                }
            }
        }
    }
#undef PSTAGE

#pragma unroll
    for (int mt = 0; mt < 4; mt++)
#pragma unroll
        for (int nt = 0; nt < 4; nt++){
            int row = brow + wy*64 + mt*16 + (lane >> 2);
            int col = bcol + wx*32 + nt*8 + ((lane & 3) << 1);
            float b0 = bias[col], b1 = bias[col+1];
            float v0 = acc[mt][nt][0] + b0, v1 = acc[mt][nt][1] + b1;
            float v2 = acc[mt][nt][2] + b0, v3 = acc[mt][nt][3] + b1;
            if (of){
                *(float2*)(of + (size_t)row*DM + col)     = make_float2(v0, v1);
                *(float2*)(of + (size_t)(row+8)*DM + col) = make_float2(v2, v3);
            } else {
                uint32_t hh, ll;
                split2(v0, v1, hh, ll);
                oh[(size_t)row*512 + (col>>1)] = hh; ol[(size_t)row*512 + (col>>1)] = ll;
                split2(v2, v3, hh, ll);
                oh[(size_t)(row+8)*512 + (col>>1)] = hh; ol[(size_t)(row+8)*512 + (col>>1)] = ll;
            }
        }
}

// merged Q/K/V projection: blockIdx.z selects stream
__global__ __launch_bounds__(256, 2) void proj_qkv(
    const float* __restrict__ bq, const float* __restrict__ bk,
    const float* __restrict__ bv)
{
    __shared__ uint32_t S[16384];
    const int z = blockIdx.z;
    const uint32_t* Ah = g_xh + (size_t)z*MR*512;
    const uint32_t* Al = g_xl + (size_t)z*MR*512;
    const uint32_t* Bh = g_wth + (size_t)z*DM*512;
    const uint32_t* Bl = g_wtl + (size_t)z*DM*512;
    const float* bias = (z == 0) ? bq : (z == 1) ? bk : bv;
    uint32_t* oh = (z == 0) ? g_Qh : (z == 1) ? g_Kh : g_Vh;
    uint32_t* ol = (z == 0) ? g_Ql : (z == 1) ? g_Kl : g_Vl;
    proj_body(Ah, Al, Bh, Bl, bias, oh, ol, nullptr, S);
}

// output projection (f32 out)
__global__ __launch_bounds__(256, 2) void proj_wo(const float* __restrict__ bo,
                                                  float* __restrict__ out)
{
    __shared__ uint32_t S[16384];
    proj_body(g_Aoh, g_Aol, g_wth + (size_t)3*DM*512, g_wtl + (size_t)3*DM*512,
              bo, nullptr, nullptr, out, S);
}

// ---------------------------------------------------------------------------
// colstats: per-key-column max/sumexp over all queries (softmax over q axis).
// K frags direct from global; Q via cp.async double-buffered smem tiles.
// ---------------------------------------------------------------------------
__global__ __launch_bounds__(256, 2) void colstats(float* __restrict__ cm,
                                                   float* __restrict__ cr)
{
    __shared__ uint32_t S[16384];
    const int tid = threadIdx.x, lane = tid & 31, w = tid >> 5;
    const int bh = blockIdx.x, kt0 = blockIdx.y << 7;
    const int b = bh >> 4, h = bh & 15;
    const uint32_t sb = smem_u32(S);

    uint2 kbh[2][4], kbl[2][4];
#pragma unroll
    for (int nt2 = 0; nt2 < 2; nt2++)
#pragma unroll
        for (int kc = 0; kc < 4; kc++){
            int key = kt0 + w*16 + nt2*8 + (lane >> 2);
            size_t o = (size_t)(b*SSQ + key)*512 + h*32 + kc*8 + (lane & 3);
            kbh[nt2][kc] = make_uint2(g_Kh[o], g_Kh[o+4]);
            kbl[nt2][kc] = make_uint2(g_Kl[o], g_Kl[o+4]);
        }

    const int srow = tid >> 1, sh = tid & 1;
    const int sw = (srow >> 1) & 3;
    const int st0 = (srow << 4) + (((2*sh)   ^ sw) << 2);
    const int st1 = (srow << 4) + (((2*sh+1) ^ sw) << 2);

#define QSTAGE(qt, B) do { \
        _Pragma("unroll") \
        for (int arr = 0; arr < 2; arr++){ \
            _Pragma("unroll") \
            for (int dblk = 0; dblk < 2; dblk++){ \
                const uint32_t* src = (arr ? g_Ql : g_Qh) \
                    + (size_t)(b*SSQ + (qt)*128 + srow)*512 + h*32 + dblk*16 + sh*8; \
                int base = (B) + arr*4096 + dblk*2048; \
                cpa16(sb + 4*(base + st0), src); \
                cpa16(sb + 4*(base + st1), src + 4); \
            } \
        } \
        CP_COMMIT; } while(0)

    float mst[4] = {-1e30f, -1e30f, -1e30f, -1e30f};
    float zst[4] = {0.f, 0.f, 0.f, 0.f};

    QSTAGE(0, 0);

    for (int qt = 0; qt < 16; qt++){
        const int B = (qt & 1) << 13;
        CP_WAIT0;
        __syncthreads();
        if (qt < 15) QSTAGE(qt + 1, ((qt + 1) & 1) << 13);

        float acc[8][2][4];
#pragma unroll
        for (int mt = 0; mt < 8; mt++)
#pragma unroll
            for (int nt2 = 0; nt2 < 2; nt2++)
#pragma unroll
                for (int j = 0; j < 4; j++) acc[mt][nt2][j] = 0.f;

#pragma unroll
        for (int mt = 0; mt < 8; mt++)
#pragma unroll
            for (int kcd = 0; kcd < 4; kcd++){
                int dblk = kcd >> 1, kc = kcd & 1;
                uint32_t qh[4], ql[4];
                int rA = mt*16 + (lane & 15);
                int cA = 2*kc + (lane >> 4);
                uint32_t ad = sb + 4*(B + dblk*2048 + swo(rA, cA));
                ldsm4(qh, ad);
                ldsm4(ql, ad + 4096*4);
#pragma unroll
                for (int nt2 = 0; nt2 < 2; nt2++){
                    mma16(acc[mt][nt2], qh[0],qh[1],qh[2],qh[3], kbh[nt2][kcd].x, kbh[nt2][kcd].y);
                    mma16(acc[mt][nt2], ql[0],ql[1],ql[2],ql[3], kbh[nt2][kcd].x, kbh[nt2][kcd].y);
                    mma16(acc[mt][nt2], qh[0],qh[1],qh[2],qh[3], kbl[nt2][kcd].x, kbl[nt2][kcd].y);
                }
            }

#pragma unroll
        for (int nt2 = 0; nt2 < 2; nt2++)
#pragma unroll
            for (int hh = 0; hh < 2; hh++){
                int si = nt2*2 + hh;
                float tmax = -1e30f;
#pragma unroll
                for (int mt = 0; mt < 8; mt++)
                    tmax = fmaxf(tmax, fmaxf(acc[mt][nt2][hh], acc[mt][nt2][hh+2]));
                tmax = fmaxf(tmax, __shfl_xor_sync(0xffffffffu, tmax, 4));
                tmax = fmaxf(tmax, __shfl_xor_sync(0xffffffffu, tmax, 8));
                tmax = fmaxf(tmax, __shfl_xor_sync(0xffffffffu, tmax, 16));
                float mn = fmaxf(mst[si], tmax);
                float ts = 0.f;
#pragma unroll
                for (int mt = 0; mt < 8; mt++)
                    ts += __expf(acc[mt][nt2][hh] - mn) + __expf(acc[mt][nt2][hh+2] - mn);
                ts += __shfl_xor_sync(0xffffffffu, ts, 4);
                ts += __shfl_xor_sync(0xffffffffu, ts, 8);
                ts += __shfl_xor_sync(0xffffffffu, ts, 16);
                zst[si] = zst[si] * __expf(mst[si] - mn) + ts;
                mst[si] = mn;
            }
    }
#undef QSTAGE

    if (lane < 4){
#pragma unroll
        for (int nt2 = 0; nt2 < 2; nt2++)
#pragma unroll
            for (int hh = 0; hh < 2; hh++){
                int col = kt0 + w*16 + nt2*8 + lane*2 + hh;
                cm[(size_t)bh*SSQ + col] = mst[nt2*2 + hh];
                cr[(size_t)bh*SSQ + col] = 1.0f / (8.0f * zst[nt2*2 + hh]);
            }
    }
}

// ---------------------------------------------------------------------------
// attn: fused QK^T recompute + exp-scale + E@V. Q resident; K/V + stats
// cp.async double-buffered; 1 sync per k-tile. E computed per 32-key half
// (16 live regs instead of 32) to fit 2 CTAs/SM.
// ---------------------------------------------------------------------------
#define AT_U32   (8192 + 2*8224 + 2*128)
#define AT_BYTES (AT_U32*4)

__global__ __launch_bounds__(256, 2) void attn(const float* __restrict__ cm,
                                               const float* __restrict__ cr)
{
    extern __shared__ uint32_t su[];
    const uint32_t sb = smem_u32(su);
    const int tid = threadIdx.x, lane = tid & 31, w = tid >> 5;
    const int g = lane >> 2, t = lane & 3;
    const int bh = blockIdx.x, qt0 = blockIdx.y << 7;
    const int b = bh >> 4, h = bh & 15;

    // stage Q resident
    {
        const int srow = tid >> 1, sh = tid & 1;
        const int sw = (srow >> 1) & 3;
        const int st0 = (srow << 4) + (((2*sh)   ^ sw) << 2);
        const int st1 = (srow << 4) + (((2*sh+1) ^ sw) << 2);
#pragma unroll
        for (int arr = 0; arr < 2; arr++)
#pragma unroll
            for (int dblk = 0; dblk < 2; dblk++){
                const uint32_t* src = (arr ? g_Ql : g_Qh)
                    + (size_t)(b*SSQ + qt0 + srow)*512 + h*32 + dblk*16 + sh*8;
                int base = arr*4096 + dblk*2048;
                *(uint4*)&su[base + st0] = *(const uint4*)src;
                *(uint4*)&su[base + st1] = *(const uint4*)(src + 4);
            }
    }

    const int krow = tid >> 2, kdb = (tid >> 1) & 1, khh = tid & 1;
    const int ksw = (krow >> 1) & 3;
    const int kst0 = (krow << 4) + (((2*khh)   ^ ksw) << 2);
    const int kst1 = (krow << 4) + (((2*khh+1) ^ ksw) << 2);

#define KSTAGE(kt, buf) do { \
        size_t go = (size_t)(b*SSQ + (kt)*64 + krow)*512 + h*32 + kdb*16 + khh*8; \
        const uint32_t* srcs[4] = { g_Kh + go, g_Kl + go, g_Vh + go, g_Vl + go }; \
        _Pragma("unroll") \
        for (int arr = 0; arr < 4; arr++){ \
            int base = 8192 + (buf)*8224 + arr*2056 + kdb*1028; \
            cpa16(sb + 4*(base + kst0), srcs[arr]); \
            cpa16(sb + 4*(base + kst1), srcs[arr] + 4); \
        } \
        if (tid < 16) \
            cpa16(sb + 4*(24640 + (buf)*128 + tid*4), cm + (size_t)bh*SSQ + (kt)*64 + tid*4); \
        else if (tid < 32) \
            cpa16(sb + 4*(24640 + (buf)*128 + 64 + (tid-16)*4), cr + (size_t)bh*SSQ + (kt)*64 + (tid-16)*4); \
        CP_COMMIT; } while(0)

    float accO[8][4];
#pragma unroll
    for (int nt = 0; nt < 8; nt++)
#pragma unroll
        for (int j = 0; j < 4; j++) accO[nt][j] = 0.f;

    KSTAGE(0, 0);

    for (int kt = 0; kt < 32; kt++){
        const int buf = kt & 1;
        CP_WAIT0;
        __syncthreads();
        if (kt < 31) KSTAGE(kt + 1, buf ^ 1);

        const int kvb = 8192 + buf*8224;
        const float* mS = (const float*)(su + 24640 + buf*128);
        const float* rS = mS + 64;

        // S = Q K^T  (warp's 16 q rows x 64 keys); K frags by ldsm4 pairs
        float accs[8][4];
#pragma unroll
        for (int nt = 0; nt < 8; nt++)
#pragma unroll
            for (int j = 0; j < 4; j++) accs[nt][j] = 0.f;

#pragma unroll
        for (int kcd = 0; kcd < 4; kcd++){
            int dblk = kcd >> 1, kc = kcd & 1;
            uint32_t qh[4], ql[4];
            uint32_t aq = sb + 4*(dblk*2048 + swo(w*16 + (lane & 15), 2*kc + (lane >> 4)));
            ldsm4(qh, aq);
            ldsm4(ql, aq + 4096*4);
            int rK = lane & 7;
            int cK = 2*kc + ((lane >> 3) & 1);
            int ntSel = lane >> 4;
#pragma unroll
            for (int ntp = 0; ntp < 4; ntp++){
                int ntX = 2*ntp + ntSel;
                uint32_t ak = sb + 4*(kvb + dblk*1028 + swo(ntX*8 + rK, cK));
                uint32_t kfh[4], kfl[4];
                ldsm4(kfh, ak);
                ldsm4(kfl, ak + 2056*4);
                mma16(accs[2*ntp],   qh[0],qh[1],qh[2],qh[3], kfh[0], kfh[1]);
                mma16(accs[2*ntp],   ql[0],ql[1],ql[2],ql[3], kfh[0], kfh[1]);
                mma16(accs[2*ntp],   qh[0],qh[1],qh[2],qh[3], kfl[0], kfl[1]);
                mma16(accs[2*ntp+1], qh[0],qh[1],qh[2],qh[3], kfh[2], kfh[3]);
                mma16(accs[2*ntp+1], ql[0],ql[1],ql[2],ql[3], kfh[2], kfh[3]);
                mma16(accs[2*ntp+1], qh[0],qh[1],qh[2],qh[3], kfl[2], kfl[3]);
            }
        }

        // per 32-key half: compute E (16 live regs) and immediately apply E@V
#pragma unroll
        for (int kp = 0; kp < 2; kp++){
            uint32_t EH2[2][4], EL2[2][4];
#pragma unroll
            for (int ntl = 0; ntl < 4; ntl++){
                int nt = 4*kp + ntl;
                int kcl = ntl >> 1, rb = (ntl & 1) << 1;
                int c0 = nt*8 + t*2, c1 = c0 + 1;
                float m0 = mS[c0], m1 = mS[c1], r0 = rS[c0], r1 = rS[c1];
                float e00 = __expf(accs[nt][0] - m0) * r0;
                float e01 = __expf(accs[nt][1] - m1) * r1;
                float e10 = __expf(accs[nt][2] - m0) * r0;
                float e11 = __expf(accs[nt][3] - m1) * r1;
                uint32_t hh, ll;
                split2(e00, e01, hh, ll); EH2[kcl][rb]   = hh; EL2[kcl][rb]   = ll;
                split2(e10, e11, hh, ll); EH2[kcl][rb+1] = hh; EL2[kcl][rb+1] = ll;
            }
#pragma unroll
            for (int ntd = 0; ntd < 8; ntd++){
                int dbd = ntd >> 2, ch = ntd & 3;
                uint32_t vh4[4], vl4[4];
                uint32_t av = sb + 4*(kvb + 2*2056 + dbd*1028 + swo(kp*32 + lane, ch));
                ldsm4t(vh4, av);
                ldsm4t(vl4, av + 2056*4);
                mma16(accO[ntd], EH2[0][0],EH2[0][1],EH2[0][2],EH2[0][3], vh4[0], vh4[1]);
                mma16(accO[ntd], EL2[0][0],EL2[0][1],EL2[0][2],EL2[0][3], vh4[0], vh4[1]);
                mma16(accO[ntd], EH2[0][0],EH2[0][1],EH2[0][2],EH2[0][3], vl4[0], vl4[1]);
                mma16(accO[ntd], EH2[1][0],EH2[1][1],EH2[1][2],EH2[1][3], vh4[2], vh4[3]);
                mma16(accO[ntd], EL2[1][0],EL2[1][1],EL2[1][2],EL2[1][3], vh4[2], vh4[3]);
                mma16(accO[ntd], EH2[1][0],EH2[1][1],EH2[1][2],EH2[1][3], vl4[2], vl4[3]);
            }
        }
    }
#undef KSTAGE

    // write split Ao
    const int row = qt0 + w*16 + g;
#pragma unroll
    for (int nt = 0; nt < 8; nt++){
        int col = nt*8 + t*2;
        uint32_t hh, ll;
        split2(accO[nt][0], accO[nt][1], hh, ll);
        g_Aoh[(size_t)(b*SSQ + row)*512 + h*32 + (col>>1)] = hh;
        g_Aol[(size_t)(b*SSQ + row)*512 + h*32 + (col>>1)] = ll;
        split2(accO[nt][2], accO[nt][3], hh, ll);
        g_Aoh[(size_t)(b*SSQ + row + 8)*512 + h*32 + (col>>1)] = hh;
        g_Aol[(size_t)(b*SSQ + row + 8)*512 + h*32 + (col>>1)] = ll;
    }
}

// ---------------------------------------------------------------------------
// Launch
// ---------------------------------------------------------------------------
extern "C" void kernel_launch(void* const* d_in, const int* in_sizes, int n_in,
                              void* d_out, int out_size)
{
    const float* qin = (const float*)d_in[0];
    const float* kin = (const float*)d_in[1];
    const float* vin = (const float*)d_in[2];
    const float* Wq  = (const float*)d_in[3];
    const float* bq  = (const float*)d_in[4];
    const float* Wk  = (const float*)d_in[5];
    const float* bk  = (const float*)d_in[6];
    const float* Wv  = (const float*)d_in[7];
    const float* bv  = (const float*)d_in[8];
    const float* Wo  = (const float*)d_in[9];
    const float* bo  = (const float*)d_in[10];

    uint32_t *wth, *wtl;
    float *cm, *cr;
    cudaGetSymbolAddress((void**)&wth, g_wth);
    cudaGetSymbolAddress((void**)&wtl, g_wtl);
    cudaGetSymbolAddress((void**)&cm,  g_cm);
    cudaGetSymbolAddress((void**)&cr,  g_cr);

    cudaFuncSetAttribute(attn, cudaFuncAttributeMaxDynamicSharedMemorySize, AT_BYTES);

    const size_t WS = (size_t)DM*512;

    inprep3<<<dim3(MR*512/256, 3), 256>>>(qin, kin, vin);

    dim3 gW(16, 32);
    wprep<<<gW, 256>>>(Wq, wth + 0*WS, wtl + 0*WS);
    wprep<<<gW, 256>>>(Wk, wth + 1*WS, wtl + 1*WS);
    wprep<<<gW, 256>>>(Wv, wth + 2*WS, wtl + 2*WS);
    wprep<<<gW, 256>>>(Wo, wth + 3*WS, wtl + 3*WS);

    proj_qkv<<<dim3(DM/128, MR/128, 3), 256>>>(bq, bk, bv);

    colstats<<<dim3(BB*NH, SSQ/128), 256>>>(cm, cr);

    attn<<<dim3(BB*NH, SSQ/128), 256, AT_BYTES>>>(cm, cr);

    proj_wo<<<dim3(DM/128, MR/128), 256>>>(bo, (float*)d_out);
}

// round 10
// speedup vs baseline: 3.2091x; 1.7516x over previous
#include <cuda_runtime.h>
#include <cuda_bf16.h>
#include <cuda_fp16.h>
#include <stdint.h>

#define BB 4
#define SSQ 2048
#define DM 1024
#define NH 16
#define MR (BB*SSQ)

// ---------------------------------------------------------------------------
// Scratch
// ---------------------------------------------------------------------------
__device__ uint32_t g_wth[2*DM*512], g_wtl[2*DM*512];   // Wq,Wk transposed, bf16 split
__device__ uint32_t g_wtf[2*DM*512];                    // Wv,Wo transposed, fp16
__device__ uint32_t g_xh[2u*MR*512], g_xl[2u*MR*512];   // q,k inputs bf16 split
__device__ uint32_t g_xf[MR*512];                       // v input fp16
__device__ uint32_t g_Qf[MR*512], g_Kf[MR*512], g_Vf[MR*512], g_Aof[MR*512];
__device__ float g_cm[BB*NH*SSQ], g_cr[BB*NH*SSQ];

// ---------------------------------------------------------------------------
// helpers
// ---------------------------------------------------------------------------
__device__ __forceinline__ void split2(float x, float y, uint32_t& hi, uint32_t& lo){
    __nv_bfloat16 hx = __float2bfloat16(x);
    __nv_bfloat16 hy = __float2bfloat16(y);
    float rx = x - __bfloat162float(hx);
    float ry = y - __bfloat162float(hy);
    __nv_bfloat162 h2 = __halves2bfloat162(hx, hy);
    __nv_bfloat162 l2 = __halves2bfloat162(__float2bfloat16(rx), __float2bfloat16(ry));
    hi = *reinterpret_cast<uint32_t*>(&h2);
    lo = *reinterpret_cast<uint32_t*>(&l2);
}
__device__ __forceinline__ uint32_t packf16(float x, float y){
    __half2 h = __floats2half2_rn(x, y);
    return *reinterpret_cast<uint32_t*>(&h);
}

__device__ __forceinline__ void mma16(float* d,
    uint32_t a0, uint32_t a1, uint32_t a2, uint32_t a3, uint32_t b0, uint32_t b1)
{
    asm volatile(
        "mma.sync.aligned.m16n8k16.row.col.f32.bf16.bf16.f32 "
        "{%0,%1,%2,%3}, {%4,%5,%6,%7}, {%8,%9}, {%0,%1,%2,%3};\n"
        : "+f"(d[0]), "+f"(d[1]), "+f"(d[2]), "+f"(d[3])
        : "r"(a0), "r"(a1), "r"(a2), "r"(a3), "r"(b0), "r"(b1));
}
__device__ __forceinline__ void mmah(float* d,
    uint32_t a0, uint32_t a1, uint32_t a2, uint32_t a3, uint32_t b0, uint32_t b1)
{
    asm volatile(
        "mma.sync.aligned.m16n8k16.row.col.f32.f16.f16.f32 "
        "{%0,%1,%2,%3}, {%4,%5,%6,%7}, {%8,%9}, {%0,%1,%2,%3};\n"
        : "+f"(d[0]), "+f"(d[1]), "+f"(d[2]), "+f"(d[3])
        : "r"(a0), "r"(a1), "r"(a2), "r"(a3), "r"(b0), "r"(b1));
}

__device__ __forceinline__ uint32_t smem_u32(const void* p){
    uint32_t a;
    asm("{ .reg .u64 t; cvta.to.shared.u64 t, %1; cvt.u32.u64 %0, t; }" : "=r"(a) : "l"(p));
    return a;
}
__device__ __forceinline__ void ldsm4(uint32_t* r, uint32_t addr){
    asm volatile("ldmatrix.sync.aligned.m8n8.x4.shared.b16 {%0,%1,%2,%3}, [%4];"
        : "=r"(r[0]), "=r"(r[1]), "=r"(r[2]), "=r"(r[3]) : "r"(addr));
}
__device__ __forceinline__ void ldsm4t(uint32_t* r, uint32_t addr){
    asm volatile("ldmatrix.sync.aligned.m8n8.x4.trans.shared.b16 {%0,%1,%2,%3}, [%4];"
        : "=r"(r[0]), "=r"(r[1]), "=r"(r[2]), "=r"(r[3]) : "r"(addr));
}
__device__ __forceinline__ void cpa16(uint32_t dst, const void* src){
    asm volatile("cp.async.cg.shared.global [%0], [%1], 16;\n" :: "r"(dst), "l"(src));
}
#define CP_COMMIT asm volatile("cp.async.commit_group;\n" ::: "memory")
#define CP_WAIT0  asm volatile("cp.async.wait_group 0;\n" ::: "memory")

__device__ __forceinline__ int swo(int r, int c){
    return (r << 4) + (((c ^ ((r >> 1) & 3))) << 2);
}

// ---------------------------------------------------------------------------
// prepass
// ---------------------------------------------------------------------------
__global__ __launch_bounds__(256) void inprep3(const float* __restrict__ q,
    const float* __restrict__ k, const float* __restrict__ v)
{
    const int y = blockIdx.y;
    size_t i = (size_t)blockIdx.x*256 + threadIdx.x;
    if (y < 2){
        const float* in = y ? k : q;
        float2 vv = *(const float2*)(in + 2*i);
        uint32_t hh, ll; split2(vv.x, vv.y, hh, ll);
        g_xh[(size_t)y*MR*512 + i] = hh;
        g_xl[(size_t)y*MR*512 + i] = ll;
    } else {
        float2 vv = *(const float2*)(v + 2*i);
        g_xf[i] = packf16(vv.x, vv.y);
    }
}

// W [k][n] -> transposed split bf16 (Wq,Wk)
__global__ __launch_bounds__(256) void wprep(const float* __restrict__ Wq,
                                             const float* __restrict__ Wk)
{
    __shared__ float t[64][33];
    const int z = blockIdx.z;
    const float* W = z ? Wk : Wq;
    const int k0 = blockIdx.x << 6, n0 = blockIdx.y << 5;
    const int tid = threadIdx.x;
#pragma unroll
    for (int i = 0; i < 8; i++){
        int v = i*256 + tid;
        t[v >> 5][v & 31] = W[(size_t)(k0 + (v >> 5))*DM + n0 + (v & 31)];
    }
    __syncthreads();
    const int n = tid >> 3, pi = (tid & 7) << 2;
    uint4 H, L; uint32_t h, l;
    split2(t[2*pi][n],   t[2*pi+1][n], h, l); H.x = h; L.x = l;
    split2(t[2*pi+2][n], t[2*pi+3][n], h, l); H.y = h; L.y = l;
    split2(t[2*pi+4][n], t[2*pi+5][n], h, l); H.z = h; L.z = l;
    split2(t[2*pi+6][n], t[2*pi+7][n], h, l); H.w = h; L.w = l;
    size_t o = (size_t)z*DM*512 + (size_t)(n0 + n)*512 + (k0 >> 1) + pi;
    *(uint4*)(g_wth + o) = H;
    *(uint4*)(g_wtl + o) = L;
}

// W [k][n] -> transposed fp16 (Wv,Wo)
__global__ __launch_bounds__(256) void wprep_f(const float* __restrict__ Wv,
                                               const float* __restrict__ Wo)
{
    __shared__ float t[64][33];
    const int z = blockIdx.z;
    const float* W = z ? Wo : Wv;
    const int k0 = blockIdx.x << 6, n0 = blockIdx.y << 5;
    const int tid = threadIdx.x;
#pragma unroll
    for (int i = 0; i < 8; i++){
        int v = i*256 + tid;
        t[v >> 5][v & 31] = W[(size_t)(k0 + (v >> 5))*DM + n0 + (v & 31)];
    }
    __syncthreads();
    const int n = tid >> 3, pi = (tid & 7) << 2;
    uint4 H;
    H.x = packf16(t[2*pi][n],   t[2*pi+1][n]);
    H.y = packf16(t[2*pi+2][n], t[2*pi+3][n]);
    H.z = packf16(t[2*pi+4][n], t[2*pi+5][n]);
    H.w = packf16(t[2*pi+6][n], t[2*pi+7][n]);
    *(uint4*)(g_wtf + (size_t)z*DM*512 + (size_t)(n0 + n)*512 + (k0 >> 1) + pi) = H;
}

// ---------------------------------------------------------------------------
// proj_bf3: exact 3-pass split-bf16 GEMM, fp16 out. For Q (z=0) and K (z=1).
// ---------------------------------------------------------------------------
__global__ __launch_bounds__(256, 2) void proj_bf3(
    const float* __restrict__ bq, const float* __restrict__ bk)
{
    __shared__ uint32_t S[16384];
    const int z = blockIdx.z;
    const uint32_t* Ah = g_xh + (size_t)z*MR*512;
    const uint32_t* Al = g_xl + (size_t)z*MR*512;
    const uint32_t* Bh = g_wth + (size_t)z*DM*512;
    const uint32_t* Bl = g_wtl + (size_t)z*DM*512;
    const float* bias = z ? bk : bq;
    uint32_t* oh = z ? g_Kf : g_Qf;

    const int tid = threadIdx.x, lane = tid & 31, w = tid >> 5;
    const int wy = w >> 2, wx = w & 3;
    const int brow = blockIdx.y << 7, bcol = blockIdx.x << 7;
    const uint32_t sb = smem_u32(S);

    const int srow = tid >> 1, sh = tid & 1;
    const int sw = (srow >> 1) & 3;
    const int st0 = (srow << 4) + (((2*sh)   ^ sw) << 2);
    const int st1 = (srow << 4) + (((2*sh+1) ^ sw) << 2);

    const uint32_t* gA0 = Ah + (size_t)(brow + srow)*512 + sh*8;
    const uint32_t* gA1 = Al + (size_t)(brow + srow)*512 + sh*8;
    const uint32_t* gB0 = Bh + (size_t)(bcol + srow)*512 + sh*8;
    const uint32_t* gB1 = Bl + (size_t)(bcol + srow)*512 + sh*8;

#define PSTAGE(s, B) do { \
        int o = (s) << 4; \
        cpa16(sb + 4*((B) + st0),        gA0 + o); cpa16(sb + 4*((B) + st1),        gA0 + o + 4); \
        cpa16(sb + 4*((B) + 2048 + st0), gA1 + o); cpa16(sb + 4*((B) + 2048 + st1), gA1 + o + 4); \
        cpa16(sb + 4*((B) + 4096 + st0), gB0 + o); cpa16(sb + 4*((B) + 4096 + st1), gB0 + o + 4); \
        cpa16(sb + 4*((B) + 6144 + st0), gB1 + o); cpa16(sb + 4*((B) + 6144 + st1), gB1 + o + 4); \
        CP_COMMIT; } while(0)

    float acc[4][4][4];
#pragma unroll
    for (int mt = 0; mt < 4; mt++)
#pragma unroll
        for (int nt = 0; nt < 4; nt++)
#pragma unroll
            for (int j = 0; j < 4; j++) acc[mt][nt][j] = 0.f;

    PSTAGE(0, 0);

    for (int it = 0; it < 32; it++){
        const int B = (it & 1) << 13;
        CP_WAIT0;
        __syncthreads();
        if (it < 31) PSTAGE(it + 1, ((it + 1) & 1) << 13);

        uint32_t bhv[4][4], blv[4][4];
#pragma unroll
        for (int nt = 0; nt < 4; nt++){
            int rB = wx*32 + nt*8 + (lane & 7);
            int cB = lane >> 3;
            uint32_t ad = sb + 4*(B + 4096 + swo(rB, cB));
            ldsm4(bhv[nt], ad);
            ldsm4(blv[nt], ad + 2048*4);
        }
#pragma unroll
        for (int kc = 0; kc < 2; kc++){
#pragma unroll
            for (int mt = 0; mt < 4; mt++){
                uint32_t ahv[4], alv[4];
                int rA = wy*64 + mt*16 + (lane & 15);
                int cA = 2*kc + (lane >> 4);
                uint32_t ad = sb + 4*(B + swo(rA, cA));
                ldsm4(ahv, ad);
                ldsm4(alv, ad + 2048*4);
#pragma unroll
                for (int nt = 0; nt < 4; nt++){
                    mma16(acc[mt][nt], ahv[0],ahv[1],ahv[2],ahv[3], bhv[nt][2*kc], bhv[nt][2*kc+1]);
                    mma16(acc[mt][nt], alv[0],alv[1],alv[2],alv[3], bhv[nt][2*kc], bhv[nt][2*kc+1]);
                    mma16(acc[mt][nt], ahv[0],ahv[1],ahv[2],ahv[3], blv[nt][2*kc], blv[nt][2*kc+1]);
                }
            }
        }
    }
#undef PSTAGE

#pragma unroll
    for (int mt = 0; mt < 4; mt++)
#pragma unroll
        for (int nt = 0; nt < 4; nt++){
            int row = brow + wy*64 + mt*16 + (lane >> 2);
            int col = bcol + wx*32 + nt*8 + ((lane & 3) << 1);
            float b0 = bias[col], b1 = bias[col+1];
            oh[(size_t)row*512 + (col>>1)] =
                packf16(acc[mt][nt][0] + b0, acc[mt][nt][1] + b1);
            oh[(size_t)(row+8)*512 + (col>>1)] =
                packf16(acc[mt][nt][2] + b0, acc[mt][nt][3] + b1);
        }
}

// ---------------------------------------------------------------------------
// proj_f16: single-pass fp16 GEMM. V projection (fp16 out) and Wo (f32 out).
// ---------------------------------------------------------------------------
__global__ __launch_bounds__(256, 2) void proj_f16(
    const uint32_t* __restrict__ Af, const uint32_t* __restrict__ Bf,
    const float* __restrict__ bias, uint32_t* __restrict__ oh,
    float* __restrict__ of)
{
    __shared__ uint32_t S[8192];   // 2 buf x (Af@0 2048, Bf@2048)
    const int tid = threadIdx.x, lane = tid & 31, w = tid >> 5;
    const int wy = w >> 2, wx = w & 3;
    const int brow = blockIdx.y << 7, bcol = blockIdx.x << 7;
    const uint32_t sb = smem_u32(S);

    const int srow = tid >> 1, sh = tid & 1;
    const int sw = (srow >> 1) & 3;
    const int st0 = (srow << 4) + (((2*sh)   ^ sw) << 2);
    const int st1 = (srow << 4) + (((2*sh+1) ^ sw) << 2);

    const uint32_t* gA = Af + (size_t)(brow + srow)*512 + sh*8;
    const uint32_t* gB = Bf + (size_t)(bcol + srow)*512 + sh*8;

#define FSTAGE(s, B) do { \
        int o = (s) << 4; \
        cpa16(sb + 4*((B) + st0),        gA + o); cpa16(sb + 4*((B) + st1),        gA + o + 4); \
        cpa16(sb + 4*((B) + 2048 + st0), gB + o); cpa16(sb + 4*((B) + 2048 + st1), gB + o + 4); \
        CP_COMMIT; } while(0)

    float acc[4][4][4];
#pragma unroll
    for (int mt = 0; mt < 4; mt++)
#pragma unroll
        for (int nt = 0; nt < 4; nt++)
#pragma unroll
            for (int j = 0; j < 4; j++) acc[mt][nt][j] = 0.f;

    FSTAGE(0, 0);

    for (int it = 0; it < 32; it++){
        const int B = (it & 1) << 12;
        CP_WAIT0;
        __syncthreads();
        if (it < 31) FSTAGE(it + 1, ((it + 1) & 1) << 12);

        uint32_t bv[4][4];
#pragma unroll
        for (int nt = 0; nt < 4; nt++){
            int rB = wx*32 + nt*8 + (lane & 7);
            ldsm4(bv[nt], sb + 4*(B + 2048 + swo(rB, lane >> 3)));
        }
#pragma unroll
        for (int kc = 0; kc < 2; kc++){
#pragma unroll
            for (int mt = 0; mt < 4; mt++){
                uint32_t av[4];
                int rA = wy*64 + mt*16 + (lane & 15);
                ldsm4(av, sb + 4*(B + swo(rA, 2*kc + (lane >> 4))));
#pragma unroll
                for (int nt = 0; nt < 4; nt++)
                    mmah(acc[mt][nt], av[0],av[1],av[2],av[3], bv[nt][2*kc], bv[nt][2*kc+1]);
            }
        }
    }
#undef FSTAGE

#pragma unroll
    for (int mt = 0; mt < 4; mt++)
#pragma unroll
        for (int nt = 0; nt < 4; nt++){
            int row = brow + wy*64 + mt*16 + (lane >> 2);
            int col = bcol + wx*32 + nt*8 + ((lane & 3) << 1);
            float b0 = bias[col], b1 = bias[col+1];
            float v0 = acc[mt][nt][0] + b0, v1 = acc[mt][nt][1] + b1;
            float v2 = acc[mt][nt][2] + b0, v3 = acc[mt][nt][3] + b1;
            if (of){
                *(float2*)(of + (size_t)row*DM + col)     = make_float2(v0, v1);
                *(float2*)(of + (size_t)(row+8)*DM + col) = make_float2(v2, v3);
            } else {
                oh[(size_t)row*512 + (col>>1)]     = packf16(v0, v1);
                oh[(size_t)(row+8)*512 + (col>>1)] = packf16(v2, v3);
            }
        }
}

// ---------------------------------------------------------------------------
// colstats: per-key-column max/sumexp over all queries. fp16 single-pass QK.
// cr carries an extra x256 to keep E in fp16 normal range.
// ---------------------------------------------------------------------------
__global__ __launch_bounds__(256, 2) void colstats(float* __restrict__ cm,
                                                   float* __restrict__ cr)
{
    __shared__ uint32_t S[8192];   // 2 buf x (2 dblk x 2048)
    const int tid = threadIdx.x, lane = tid & 31, w = tid >> 5;
    const int bh = blockIdx.x, kt0 = blockIdx.y << 7;
    const int b = bh >> 4, h = bh & 15;
    const uint32_t sb = smem_u32(S);

    uint2 kb[2][4];
#pragma unroll
    for (int nt2 = 0; nt2 < 2; nt2++)
#pragma unroll
        for (int kc = 0; kc < 4; kc++){
            int key = kt0 + w*16 + nt2*8 + (lane >> 2);
            size_t o = (size_t)(b*SSQ + key)*512 + h*32 + kc*8 + (lane & 3);
            kb[nt2][kc] = make_uint2(g_Kf[o], g_Kf[o+4]);
        }

    const int srow = tid >> 1, sh = tid & 1;
    const int sw = (srow >> 1) & 3;
    const int st0 = (srow << 4) + (((2*sh)   ^ sw) << 2);
    const int st1 = (srow << 4) + (((2*sh+1) ^ sw) << 2);

#define QSTAGE(qt, B) do { \
        _Pragma("unroll") \
        for (int dblk = 0; dblk < 2; dblk++){ \
            const uint32_t* src = g_Qf \
                + (size_t)(b*SSQ + (qt)*128 + srow)*512 + h*32 + dblk*16 + sh*8; \
            int base = (B) + dblk*2048; \
            cpa16(sb + 4*(base + st0), src); \
            cpa16(sb + 4*(base + st1), src + 4); \
        } \
        CP_COMMIT; } while(0)

    float mst[4] = {-1e30f, -1e30f, -1e30f, -1e30f};
    float zst[4] = {0.f, 0.f, 0.f, 0.f};

    QSTAGE(0, 0);

    for (int qt = 0; qt < 16; qt++){
        const int B = (qt & 1) << 12;
        CP_WAIT0;
        __syncthreads();
        if (qt < 15) QSTAGE(qt + 1, ((qt + 1) & 1) << 12);

        float acc[8][2][4];
#pragma unroll
        for (int mt = 0; mt < 8; mt++)
#pragma unroll
            for (int nt2 = 0; nt2 < 2; nt2++)
#pragma unroll
                for (int j = 0; j < 4; j++) acc[mt][nt2][j] = 0.f;

#pragma unroll
        for (int mt = 0; mt < 8; mt++)
#pragma unroll
            for (int kcd = 0; kcd < 4; kcd++){
                int dblk = kcd >> 1, kc = kcd & 1;
                uint32_t qf[4];
                int rA = mt*16 + (lane & 15);
                int cA = 2*kc + (lane >> 4);
                ldsm4(qf, sb + 4*(B + dblk*2048 + swo(rA, cA)));
#pragma unroll
                for (int nt2 = 0; nt2 < 2; nt2++)
                    mmah(acc[mt][nt2], qf[0],qf[1],qf[2],qf[3], kb[nt2][kcd].x, kb[nt2][kcd].y);
            }

#pragma unroll
        for (int nt2 = 0; nt2 < 2; nt2++)
#pragma unroll
            for (int hh = 0; hh < 2; hh++){
                int si = nt2*2 + hh;
                float tmax = -1e30f;
#pragma unroll
                for (int mt = 0; mt < 8; mt++)
                    tmax = fmaxf(tmax, fmaxf(acc[mt][nt2][hh], acc[mt][nt2][hh+2]));
                tmax = fmaxf(tmax, __shfl_xor_sync(0xffffffffu, tmax, 4));
                tmax = fmaxf(tmax, __shfl_xor_sync(0xffffffffu, tmax, 8));
                tmax = fmaxf(tmax, __shfl_xor_sync(0xffffffffu, tmax, 16));
                float mn = fmaxf(mst[si], tmax);
                float ts = 0.f;
#pragma unroll
                for (int mt = 0; mt < 8; mt++)
                    ts += __expf(acc[mt][nt2][hh] - mn) + __expf(acc[mt][nt2][hh+2] - mn);
                ts += __shfl_xor_sync(0xffffffffu, ts, 4);
                ts += __shfl_xor_sync(0xffffffffu, ts, 8);
                ts += __shfl_xor_sync(0xffffffffu, ts, 16);
                zst[si] = zst[si] * __expf(mst[si] - mn) + ts;
                mst[si] = mn;
            }
    }
#undef QSTAGE

    if (lane < 4){
#pragma unroll
        for (int nt2 = 0; nt2 < 2; nt2++)
#pragma unroll
            for (int hh = 0; hh < 2; hh++){
                int col = kt0 + w*16 + nt2*8 + lane*2 + hh;
                cm[(size_t)bh*SSQ + col] = mst[nt2*2 + hh];
                // 256/(8*Z): extra x256 keeps E in fp16 normal range
                cr[(size_t)bh*SSQ + col] = 32.0f / zst[nt2*2 + hh];
            }
    }
}

// ---------------------------------------------------------------------------
// attn: QK^T (fp16 1-pass) + exp-scale + E@V (fp16 1-pass). Q resident.
// smem u32: Qf@0 (4096); buf b @4096+b*4240: Kf 2056 | Vf 2056 | stats 128
// ---------------------------------------------------------------------------
#define AT_U32   (4096 + 2*4240)
#define AT_BYTES (AT_U32*4)

__global__ __launch_bounds__(256, 2) void attn(const float* __restrict__ cm,
                                               const float* __restrict__ cr)
{
    extern __shared__ uint32_t su[];
    const uint32_t sb = smem_u32(su);
    const int tid = threadIdx.x, lane = tid & 31, w = tid >> 5;
    const int g = lane >> 2, t = lane & 3;
    const int bh = blockIdx.x, qt0 = blockIdx.y << 7;
    const int b = bh >> 4, h = bh & 15;

    // stage Q resident (fp16 single)
    {
        const int srow = tid >> 1, sh = tid & 1;
        const int sw = (srow >> 1) & 3;
        const int st0 = (srow << 4) + (((2*sh)   ^ sw) << 2);
        const int st1 = (srow << 4) + (((2*sh+1) ^ sw) << 2);
#pragma unroll
        for (int dblk = 0; dblk < 2; dblk++){
            const uint32_t* src = g_Qf
                + (size_t)(b*SSQ + qt0 + srow)*512 + h*32 + dblk*16 + sh*8;
            su[dblk*2048 + st0] = src[0]; su[dblk*2048 + st0 + 1] = src[1];
            su[dblk*2048 + st0 + 2] = src[2]; su[dblk*2048 + st0 + 3] = src[3];
            su[dblk*2048 + st1] = src[4]; su[dblk*2048 + st1 + 1] = src[5];
            su[dblk*2048 + st1 + 2] = src[6]; su[dblk*2048 + st1 + 3] = src[7];
        }
    }

    const int krow = tid >> 2, kdb = (tid >> 1) & 1, khh = tid & 1;
    const int ksw = (krow >> 1) & 3;
    const int kst0 = (krow << 4) + (((2*khh)   ^ ksw) << 2);
    const int kst1 = (krow << 4) + (((2*khh+1) ^ ksw) << 2);

#define KSTAGE(kt, buf) do { \
        size_t go = (size_t)(b*SSQ + (kt)*64 + krow)*512 + h*32 + kdb*16 + khh*8; \
        int kb0 = 4096 + (buf)*4240 + kdb*1028; \
        cpa16(sb + 4*(kb0 + kst0), g_Kf + go); \
        cpa16(sb + 4*(kb0 + kst1), g_Kf + go + 4); \
        cpa16(sb + 4*(kb0 + 2056 + kst0), g_Vf + go); \
        cpa16(sb + 4*(kb0 + 2056 + kst1), g_Vf + go + 4); \
        if (tid < 16) \
            cpa16(sb + 4*(4096 + (buf)*4240 + 4112 + tid*4), cm + (size_t)bh*SSQ + (kt)*64 + tid*4); \
        else if (tid < 32) \
            cpa16(sb + 4*(4096 + (buf)*4240 + 4176 + (tid-16)*4), cr + (size_t)bh*SSQ + (kt)*64 + (tid-16)*4); \
        CP_COMMIT; } while(0)

    float accO[8][4];
#pragma unroll
    for (int nt = 0; nt < 8; nt++)
#pragma unroll
        for (int j = 0; j < 4; j++) accO[nt][j] = 0.f;

    KSTAGE(0, 0);

    for (int kt = 0; kt < 32; kt++){
        const int buf = kt & 1;
        CP_WAIT0;
        __syncthreads();
        if (kt < 31) KSTAGE(kt + 1, buf ^ 1);

        const int Kb = 4096 + buf*4240;
        const int Vb = Kb + 2056;
        const float* mS = (const float*)(su + Kb + 4112);
        const float* rS = (const float*)(su + Kb + 4176);

        // S = Q K^T (fp16, single pass): warp's 16 q rows x 64 keys
        float accs[8][4];
#pragma unroll
        for (int nt = 0; nt < 8; nt++)
#pragma unroll
            for (int j = 0; j < 4; j++) accs[nt][j] = 0.f;

#pragma unroll
        for (int kcd = 0; kcd < 4; kcd++){
            int dblk = kcd >> 1, kc = kcd & 1;
            uint32_t qf[4];
            ldsm4(qf, sb + 4*(dblk*2048 + swo(w*16 + (lane & 15), 2*kc + (lane >> 4))));
            int rK = lane & 7;
            int cK = 2*kc + ((lane >> 3) & 1);
            int ntSel = lane >> 4;
#pragma unroll
            for (int ntp = 0; ntp < 4; ntp++){
                int ntX = 2*ntp + ntSel;
                uint32_t kf[4];
                ldsm4(kf, sb + 4*(Kb + dblk*1028 + swo(ntX*8 + rK, cK)));
                mmah(accs[2*ntp],   qf[0],qf[1],qf[2],qf[3], kf[0], kf[1]);
                mmah(accs[2*ntp+1], qf[0],qf[1],qf[2],qf[3], kf[2], kf[3]);
            }
        }

        // per 32-key half: E (fp16, x256-scaled) then E@V single pass
#pragma unroll
        for (int kp = 0; kp < 2; kp++){
            uint32_t EF[2][4];
#pragma unroll
            for (int ntl = 0; ntl < 4; ntl++){
                int nt = 4*kp + ntl;
                int kcl = ntl >> 1, rb = (ntl & 1) << 1;
                int c0 = nt*8 + t*2, c1 = c0 + 1;
                float m0 = mS[c0], m1 = mS[c1], r0 = rS[c0], r1 = rS[c1];
                float e00 = __expf(accs[nt][0] - m0) * r0;
                float e01 = __expf(accs[nt][1] - m1) * r1;
                float e10 = __expf(accs[nt][2] - m0) * r0;
                float e11 = __expf(accs[nt][3] - m1) * r1;
                EF[kcl][rb]   = packf16(e00, e01);
                EF[kcl][rb+1] = packf16(e10, e11);
            }
#pragma unroll
            for (int ntd = 0; ntd < 8; ntd++){
                int dbd = ntd >> 2, ch = ntd & 3;
                uint32_t vf[4];
                ldsm4t(vf, sb + 4*(Vb + dbd*1028 + swo(kp*32 + lane, ch)));
                mmah(accO[ntd], EF[0][0],EF[0][1],EF[0][2],EF[0][3], vf[0], vf[1]);
                mmah(accO[ntd], EF[1][0],EF[1][1],EF[1][2],EF[1][3], vf[2], vf[3]);
            }
        }
    }
#undef KSTAGE

    // write Ao fp16 (undo x256)
    const float sc = 1.0f/256.0f;
    const int row = qt0 + w*16 + g;
#pragma unroll
    for (int nt = 0; nt < 8; nt++){
        int col = nt*8 + t*2;
        g_Aof[(size_t)(b*SSQ + row)*512 + h*32 + (col>>1)] =
            packf16(accO[nt][0]*sc, accO[nt][1]*sc);
        g_Aof[(size_t)(b*SSQ + row + 8)*512 + h*32 + (col>>1)] =
            packf16(accO[nt][2]*sc, accO[nt][3]*sc);
    }
}

// ---------------------------------------------------------------------------
// Launch
// ---------------------------------------------------------------------------
extern "C" void kernel_launch(void* const* d_in, const int* in_sizes, int n_in,
                              void* d_out, int out_size)
{
    const float* qin = (const float*)d_in[0];
    const float* kin = (const float*)d_in[1];
    const float* vin = (const float*)d_in[2];
    const float* Wq  = (const float*)d_in[3];
    const float* bq  = (const float*)d_in[4];
    const float* Wk  = (const float*)d_in[5];
    const float* bk  = (const float*)d_in[6];
    const float* Wv  = (const float*)d_in[7];
    const float* bv  = (const float*)d_in[8];
    const float* Wo  = (const float*)d_in[9];
    const float* bo  = (const float*)d_in[10];

    uint32_t *xf, *wtf, *Aof, *Vf;
    float *cm, *cr;
    cudaGetSymbolAddress((void**)&xf,  g_xf);
    cudaGetSymbolAddress((void**)&wtf, g_wtf);
    cudaGetSymbolAddress((void**)&Aof, g_Aof);
    cudaGetSymbolAddress((void**)&Vf,  g_Vf);
    cudaGetSymbolAddress((void**)&cm,  g_cm);
    cudaGetSymbolAddress((void**)&cr,  g_cr);

    cudaFuncSetAttribute(attn, cudaFuncAttributeMaxDynamicSharedMemorySize, AT_BYTES);

    inprep3<<<dim3(MR*512/256, 3), 256>>>(qin, kin, vin);
    wprep  <<<dim3(16, 32, 2), 256>>>(Wq, Wk);
    wprep_f<<<dim3(16, 32, 2), 256>>>(Wv, Wo);

    proj_bf3<<<dim3(DM/128, MR/128, 2), 256>>>(bq, bk);
    proj_f16<<<dim3(DM/128, MR/128), 256>>>(xf, wtf, bv, Vf, nullptr);

    colstats<<<dim3(BB*NH, SSQ/128), 256>>>(cm, cr);

    attn<<<dim3(BB*NH, SSQ/128), 256, AT_BYTES>>>(cm, cr);

    proj_f16<<<dim3(DM/128, MR/128), 256>>>(Aof, wtf + (size_t)DM*512, bo,
                                            nullptr, (float*)d_out);
}